// round 3
// baseline (speedup 1.0000x reference)
#include <cuda_runtime.h>
#include <math.h>
#include <float.h>

#define BB   2
#define NP   16384
#define FF   32
#define MM   4096
#define KK   64
#define HH   64
#define CO   128
#define NTOT (BB*NP)
#define MTOT (BB*MM)
#define CANDMAX 2048

#define GFPS  8                 // CTAs per cloud (one cluster)
#define TFPS  256               // threads per FPS CTA
#define SHARD (NP/GFPS)         // 2048 points per CTA
#define PPT   (SHARD/TFPS)      // 8 points per thread

static __device__ float g_pc[MTOT*3];
static __device__ float g_u[NTOT*HH];
static __device__ int   g_nbr[MTOT*KK];
static __device__ int   g_cnt[MTOT];

// ---------- packed f32x2 helpers (lane-wise identical rounding to scalar fp32) ----------
__device__ __forceinline__ unsigned long long pack2(float lo, float hi) {
    unsigned long long r;
    asm("mov.b64 %0, {%1, %2};" : "=l"(r) : "r"(__float_as_uint(lo)), "r"(__float_as_uint(hi)));
    return r;
}
__device__ __forceinline__ void unpack2(unsigned long long v, float &lo, float &hi) {
    unsigned a, b;
    asm("mov.b64 {%0, %1}, %2;" : "=r"(a), "=r"(b) : "l"(v));
    lo = __uint_as_float(a); hi = __uint_as_float(b);
}
__device__ __forceinline__ unsigned long long add2(unsigned long long a, unsigned long long b) {
    unsigned long long r; asm("add.rn.f32x2 %0, %1, %2;" : "=l"(r) : "l"(a), "l"(b)); return r;
}
__device__ __forceinline__ unsigned long long mul2(unsigned long long a, unsigned long long b) {
    unsigned long long r; asm("mul.rn.f32x2 %0, %1, %2;" : "=l"(r) : "l"(a), "l"(b)); return r;
}
__device__ __forceinline__ unsigned long long fma2(unsigned long long a, unsigned long long b, unsigned long long c) {
    unsigned long long r; asm("fma.rn.f32x2 %0, %1, %2, %3;" : "=l"(r) : "l"(a), "l"(b), "l"(c)); return r;
}

// ---------- cluster helpers ----------
__device__ __forceinline__ unsigned cta_rank() {
    unsigned r; asm("mov.u32 %0, %%cluster_ctarank;" : "=r"(r)); return r;
}
__device__ __forceinline__ void cluster_sync_all() {
    asm volatile("barrier.cluster.arrive.aligned;" ::: "memory");
    asm volatile("barrier.cluster.wait.aligned;" ::: "memory");
}
__device__ __forceinline__ void st_cluster_u64(unsigned local_smem_addr, unsigned target_rank,
                                               unsigned long long v) {
    unsigned raddr;
    asm volatile("mapa.shared::cluster.u32 %0, %1, %2;" : "=r"(raddr)
                 : "r"(local_smem_addr), "r"(target_rank));
    asm volatile("st.shared::cluster.u64 [%0], %1;" :: "r"(raddr), "l"(v) : "memory");
}
__device__ __forceinline__ void mbar_init(unsigned addr, unsigned count) {
    asm volatile("mbarrier.init.shared.b64 [%0], %1;" :: "r"(addr), "r"(count) : "memory");
}
__device__ __forceinline__ void mbar_arrive_remote(unsigned local_addr, unsigned target_rank) {
    asm volatile(
        "{\n\t.reg .b32 ra;\n\t"
        "mapa.shared::cluster.u32 ra, %0, %1;\n\t"
        "mbarrier.arrive.release.cluster.shared::cluster.b64 _, [ra];\n\t}"
        :: "r"(local_addr), "r"(target_rank) : "memory");
}
__device__ __forceinline__ void mbar_wait_cluster(unsigned addr, unsigned parity) {
    asm volatile(
        "{\n\t"
        ".reg .pred P;\n\t"
        "WL_%=:\n\t"
        "mbarrier.try_wait.parity.acquire.cluster.shared::cta.b64 P, [%0], %1, 0x989680;\n\t"
        "@P bra.uni WD_%=;\n\t"
        "bra.uni WL_%=;\n\t"
        "WD_%=:\n\t"
        "}"
        :: "r"(addr), "r"(parity) : "memory");
}

// =====================================================================================
// Kernel 1: exact FPS, 8-CTA cluster per cloud. Coords + d in registers; per-iteration
// cross-CTA candidate exchange through DSMEM slots + mbarrier (double-buffered), no
// barrier.cluster on the critical path. Bit-exact vs reference: non-FMA fp32 distances;
// key = d_bits<<32 | ~global_idx (64-bit max == largest d, ties -> smallest index).
// =====================================================================================
__global__ __launch_bounds__(TFPS, 1) __cluster_dims__(GFPS, 1, 1)
void fps_kernel(const float* __restrict__ pos) {
    extern __shared__ float sh[];
    float* sx = sh;
    float* sy = sh + NP;
    float* sz = sh + 2*NP;
    __shared__ unsigned long long swarp[TFPS/32];
    __shared__ __align__(16) unsigned long long slot[2][GFPS];
    __shared__ __align__(8)  unsigned long long mbar[2];

    const int tid = threadIdx.x, lane = tid & 31, wid = tid >> 5;
    const unsigned rank = cta_rank();
    const int b = blockIdx.x / GFPS;
    const float* p = pos + (size_t)b * NP * 3;

    const unsigned slot_base = (unsigned)__cvta_generic_to_shared(&slot[0][0]);
    const unsigned mbar_base = (unsigned)__cvta_generic_to_shared(&mbar[0]);

    if (tid == 0) {
        mbar_init(mbar_base + 0, GFPS);
        mbar_init(mbar_base + 8, GFPS);
        asm volatile("fence.mbarrier_init.release.cluster;" ::: "memory");
    }

    // stage full cloud coords (SoA) into smem — winner-coord broadcast lookups
    for (int i = tid; i < NP; i += TFPS) {
        sx[i] = p[3*i]; sy[i] = p[3*i+1]; sz[i] = p[3*i+2];
    }
    __syncthreads();
    cluster_sync_all();   // mbarrier init visible cluster-wide before any remote arrive

    // own shard: coords + running min-distance in registers
    const int jbase = (int)rank * SHARD + tid;
    float mx[PPT], my[PPT], mz[PPT], d[PPT];
    const float x0 = sx[0], y0 = sy[0], z0 = sz[0];
    float bd = -FLT_MAX; int bj = 0;
#pragma unroll
    for (int k = 0; k < PPT; ++k) {
        int j = jbase + k*TFPS;
        mx[k] = sx[j]; my[k] = sy[j]; mz[k] = sz[j];
        float dx = __fsub_rn(mx[k], x0);
        float dy = __fsub_rn(my[k], y0);
        float dz = __fsub_rn(mz[k], z0);
        d[k] = __fadd_rn(__fadd_rn(__fmul_rn(dx,dx), __fmul_rn(dy,dy)), __fmul_rn(dz,dz));
        if (d[k] > bd) { bd = d[k]; bj = j; }
    }
    if (rank == 0 && tid == TFPS-1) {
        g_pc[((size_t)b*MM + 0)*3 + 0] = x0;
        g_pc[((size_t)b*MM + 0)*3 + 1] = y0;
        g_pc[((size_t)b*MM + 0)*3 + 2] = z0;
    }

    int ph0 = 0, ph1 = 0;

    for (int m = 1; m < MM; ++m) {
        const int buf = m & 1;
        // --- build key, warp reduce ---
        unsigned long long key =
            ((unsigned long long)__float_as_uint(bd) << 32) | (unsigned)(~bj);
#pragma unroll
        for (int o = 16; o > 0; o >>= 1) {
            unsigned long long v = __shfl_down_sync(0xffffffffu, key, o);
            if (v > key) key = v;
        }
        if (lane == 0) swarp[wid] = key;
        __syncthreads();
        // --- CTA reduce (8 warps) + push CTA candidate to all cluster CTAs ---
        if (wid == 0) {
            unsigned long long k2 = (lane < TFPS/32) ? swarp[lane] : 0ull;
#pragma unroll
            for (int o = 4; o > 0; o >>= 1) {
                unsigned long long v = __shfl_down_sync(0xffffffffu, k2, o);
                if (v > k2) k2 = v;
            }
            if (lane == 0) {
                const unsigned laddr = slot_base + (unsigned)(buf*GFPS + rank) * 8u;
                const unsigned maddr = mbar_base + (unsigned)buf * 8u;
#pragma unroll
                for (unsigned g = 0; g < GFPS; ++g)
                    st_cluster_u64(laddr, g, k2);
#pragma unroll
                for (unsigned g = 0; g < GFPS; ++g)
                    mbar_arrive_remote(maddr, g);
            }
        }
        // --- wait for all 8 CTA candidates ---
        if (buf == 0) { mbar_wait_cluster(mbar_base + 0, ph0); ph0 ^= 1; }
        else          { mbar_wait_cluster(mbar_base + 8, ph1); ph1 ^= 1; }
        // --- every thread picks the global winner (deterministic) ---
        unsigned long long w = slot[buf][0];
#pragma unroll
        for (int g = 1; g < GFPS; ++g) {
            unsigned long long v = slot[buf][g];
            if (v > w) w = v;
        }
        const int wj = (int)(~(unsigned)w);
        const float wx = sx[wj], wy = sy[wj], wz = sz[wj];
        if (rank == 0 && tid == TFPS-1) {
            g_pc[((size_t)b*MM + m)*3 + 0] = wx;
            g_pc[((size_t)b*MM + m)*3 + 1] = wy;
            g_pc[((size_t)b*MM + m)*3 + 2] = wz;
        }
        // --- fused packed min-update + next argmax (exact op sequence) ---
        const unsigned long long nwx = pack2(-wx, -wx);
        const unsigned long long nwy = pack2(-wy, -wy);
        const unsigned long long nwz = pack2(-wz, -wz);
        bd = -FLT_MAX; bj = 0;
#pragma unroll
        for (int k = 0; k < PPT/2; ++k) {
            unsigned long long dx = add2(pack2(mx[2*k], mx[2*k+1]), nwx);
            unsigned long long dy = add2(pack2(my[2*k], my[2*k+1]), nwy);
            unsigned long long dz = add2(pack2(mz[2*k], mz[2*k+1]), nwz);
            unsigned long long s  = add2(add2(mul2(dx,dx), mul2(dy,dy)), mul2(dz,dz));
            float s0, s1; unpack2(s, s0, s1);
            d[2*k]   = fminf(d[2*k],   s0);
            d[2*k+1] = fminf(d[2*k+1], s1);
            if (d[2*k]   > bd) { bd = d[2*k];   bj = jbase + (2*k)*TFPS; }
            if (d[2*k+1] > bd) { bd = d[2*k+1]; bj = jbase + (2*k+1)*TFPS; }
        }
    }
    cluster_sync_all();   // keep CTAs resident until all exchanges consumed
}

// =====================================================================================
// Kernel 2: per-point layer-1 partials  u_j = x_j@W1[:32] + p_j@W1[32:35] + b1
// =====================================================================================
__global__ __launch_bounds__(256) void feat_kernel(const float* __restrict__ x,
                                                   const float* __restrict__ pos,
                                                   const float* __restrict__ W1,
                                                   const float* __restrict__ b1) {
    __shared__ float xs[4][FF];
    __shared__ float ps[4][3];
    const int j0 = blockIdx.x * 4;
    const int tid = threadIdx.x;
    if (tid < 128) xs[tid >> 5][tid & 31] = x[(size_t)(j0 + (tid >> 5))*FF + (tid & 31)];
    if (tid < 12)  ps[tid / 3][tid % 3]   = pos[(size_t)j0*3 + tid];
    __syncthreads();
    const int pt = tid >> 6, h = tid & 63;
    float acc = b1[h];
#pragma unroll
    for (int f = 0; f < FF; ++f) acc += xs[pt][f] * W1[f*HH + h];
    acc += ps[pt][0] * W1[32*HH + h];
    acc += ps[pt][1] * W1[33*HH + h];
    acc += ps[pt][2] * W1[34*HH + h];
    g_u[(size_t)(j0 + pt)*HH + h] = acc;
}

// =====================================================================================
// Kernel 3: ball query. Compact in-radius candidates; if cnt<=K emit directly (set
// semantics — downstream max-agg is order-invariant); else bitonic-sort next_pow2(cnt)
// packed (d2,idx) keys and take K smallest. Tie-break identical to stable top_k.
// =====================================================================================
__global__ __launch_bounds__(256) void ballq_kernel(const float* __restrict__ pos) {
    const float R2 = (float)(0.2 * 0.2);
    const int i = blockIdx.x;
    const int b = i / MM;
    __shared__ unsigned long long cand[CANDMAX];
    __shared__ int cnt;
    const int tid = threadIdx.x;
    if (tid == 0) cnt = 0;
    const float cx = g_pc[(size_t)i*3 + 0];
    const float cy = g_pc[(size_t)i*3 + 1];
    const float cz = g_pc[(size_t)i*3 + 2];
    __syncthreads();
    const float* p = pos + (size_t)b * NP * 3;
    for (int j = tid; j < NP; j += 256) {
        float dx = __fsub_rn(cx, p[3*j]);
        float dy = __fsub_rn(cy, p[3*j+1]);
        float dz = __fsub_rn(cz, p[3*j+2]);
        float d2 = __fadd_rn(__fadd_rn(__fmul_rn(dx,dx), __fmul_rn(dy,dy)), __fmul_rn(dz,dz));
        if (d2 <= R2) {
            int sl = atomicAdd(&cnt, 1);
            if (sl < CANDMAX)
                cand[sl] = ((unsigned long long)__float_as_uint(d2) << 32) | (unsigned)j;
        }
    }
    __syncthreads();
    const int c = min(cnt, CANDMAX);
    if (c > KK) {
        int p2 = KK;
        while (p2 < c) p2 <<= 1;
        for (int t = tid; t < p2; t += 256)
            if (t >= c) cand[t] = ~0ull;
        for (int k = 2; k <= p2; k <<= 1) {
            for (int s = k >> 1; s > 0; s >>= 1) {
                __syncthreads();
                for (int t = tid; t < p2; t += 256) {
                    int pr = t ^ s;
                    if (pr > t) {
                        unsigned long long a = cand[t], bv = cand[pr];
                        bool up = ((t & k) == 0);
                        if ((a > bv) == up) { cand[t] = bv; cand[pr] = a; }
                    }
                }
            }
        }
        __syncthreads();
    }
    const int v = min(c, KK);
    if (tid < KK) g_nbr[(size_t)i*KK + tid] = (tid < v) ? (int)(unsigned)cand[tid] : 0;
    if (tid == 0) g_cnt[i] = v;
}

// =====================================================================================
// Kernel 4: layer 2 + max aggregation
// =====================================================================================
__device__ __forceinline__ float dot64(const float* __restrict__ h1,
                                       const unsigned long long* __restrict__ w2p) {
    const float2* hb = (const float2*)h1;
    unsigned long long a0 = 0ull, a1 = 0ull;
#pragma unroll
    for (int h2 = 0; h2 < HH/2; h2 += 2) {
        float2 p0 = hb[h2], p1 = hb[h2 + 1];
        a0 = fma2(pack2(p0.x, p0.y), w2p[h2],     a0);
        a1 = fma2(pack2(p1.x, p1.y), w2p[h2 + 1], a1);
    }
    float l0, u0, l1, u1;
    unpack2(a0, l0, u0); unpack2(a1, l1, u1);
    return (l0 + u0) + (l1 + u1);
}

__global__ __launch_bounds__(128) void mlp_kernel(const float* __restrict__ W1,
                                                  const float* __restrict__ W2,
                                                  const float* __restrict__ b2,
                                                  float* __restrict__ out) {
    const int i = blockIdx.x;
    const int b = i / MM;
    const int tid = threadIdx.x;
    __shared__ float v[HH];
    __shared__ float h1buf[2][HH];

    unsigned long long w2p[HH/2];
#pragma unroll
    for (int h = 0; h < HH/2; ++h)
        w2p[h] = pack2(W2[(size_t)(2*h)*CO + tid], W2[(size_t)(2*h + 1)*CO + tid]);

    if (tid < HH) {
        float icx = __fdiv_rn(g_pc[(size_t)i*3 + 0], 0.2f);
        float icy = __fdiv_rn(g_pc[(size_t)i*3 + 1], 0.2f);
        float icz = __fdiv_rn(g_pc[(size_t)i*3 + 2], 0.2f);
        v[tid] = icx*W1[32*HH + tid] + icy*W1[33*HH + tid] + icz*W1[34*HH + tid];
    }
    const int cnt = g_cnt[i];
    float mx = -FLT_MAX;
    __syncthreads();

    const int which = tid >> 6, h = tid & 63;
    for (int jj = 0; jj < cnt; jj += 2) {
        int idx = jj + which;
        if (idx < cnt) {
            int nb = g_nbr[(size_t)i*KK + idx];
            h1buf[which][h] = fmaxf(g_u[((size_t)b*NP + nb)*HH + h] - v[h], 0.0f);
        }
        __syncthreads();
        mx = fmaxf(mx, dot64(h1buf[0], w2p));
        if (jj + 1 < cnt) mx = fmaxf(mx, dot64(h1buf[1], w2p));
        __syncthreads();
    }
    float res = (cnt > 0) ? (mx + b2[tid]) : 0.0f;
    out[(size_t)i*CO + tid] = res;
}

// =====================================================================================
// Kernel 5: tail outputs (centroid positions + batch vector)
// =====================================================================================
__global__ void tail_kernel(float* __restrict__ out, int has_pc, int has_batch) {
    const int i = blockIdx.x * 256 + threadIdx.x;
    if (has_pc && i < MTOT*3) out[(size_t)MTOT*CO + i] = g_pc[i];
    if (has_batch && i < MTOT) out[(size_t)MTOT*CO + (size_t)MTOT*3 + i] = (float)(i / MM);
}

extern "C" void kernel_launch(void* const* d_in, const int* in_sizes, int n_in,
                              void* d_out, int out_size) {
    const float* x   = (const float*)d_in[0];
    const float* pos = (const float*)d_in[1];
    const float* W1  = (const float*)d_in[3];
    const float* b1  = (const float*)d_in[4];
    const float* W2  = (const float*)d_in[5];
    const float* b2  = (const float*)d_in[6];
    float* out = (float*)d_out;

    cudaFuncSetAttribute(fps_kernel, cudaFuncAttributeMaxDynamicSharedMemorySize, 3*NP*4);

    fps_kernel<<<BB*GFPS, TFPS, 3*NP*4>>>(pos);
    feat_kernel<<<NTOT/4, 256>>>(x, pos, W1, b1);
    ballq_kernel<<<MTOT, 256>>>(pos);
    mlp_kernel<<<MTOT, 128>>>(W1, W2, b2, out);

    int has_pc    = out_size >= MTOT*CO + MTOT*3;
    int has_batch = out_size >= MTOT*CO + MTOT*3 + MTOT;
    if (has_pc)
        tail_kernel<<<(MTOT*3 + 255)/256, 256>>>(out, has_pc, has_batch);
}

// round 4
// speedup vs baseline: 3.0059x; 3.0059x over previous
#include <cuda_runtime.h>
#include <math.h>
#include <float.h>

#define BB   2
#define NP   16384
#define FF   32
#define MM   4096
#define KK   64
#define HH   64
#define CO   128
#define NTOT (BB*NP)
#define MTOT (BB*MM)
#define CANDMAX 2048

#define GFPS  8                 // CTAs per cloud (one cluster)
#define TFPS  256               // threads per FPS CTA
#define SHARD (NP/GFPS)         // 2048 points per CTA
#define PPT   (SHARD/TFPS)      // 8 points per thread

static __device__ float g_pc[MTOT*3];
static __device__ float g_u[NTOT*HH];
static __device__ int   g_nbr[MTOT*KK];
static __device__ int   g_cnt[MTOT];

// ---------- packed f32x2 helpers (lane-wise identical rounding to scalar fp32) ----------
__device__ __forceinline__ unsigned long long pack2(float lo, float hi) {
    unsigned long long r;
    asm("mov.b64 %0, {%1, %2};" : "=l"(r) : "r"(__float_as_uint(lo)), "r"(__float_as_uint(hi)));
    return r;
}
__device__ __forceinline__ void unpack2(unsigned long long v, float &lo, float &hi) {
    unsigned a, b;
    asm("mov.b64 {%0, %1}, %2;" : "=r"(a), "=r"(b) : "l"(v));
    lo = __uint_as_float(a); hi = __uint_as_float(b);
}
__device__ __forceinline__ unsigned long long add2(unsigned long long a, unsigned long long b) {
    unsigned long long r; asm("add.rn.f32x2 %0, %1, %2;" : "=l"(r) : "l"(a), "l"(b)); return r;
}
__device__ __forceinline__ unsigned long long mul2(unsigned long long a, unsigned long long b) {
    unsigned long long r; asm("mul.rn.f32x2 %0, %1, %2;" : "=l"(r) : "l"(a), "l"(b)); return r;
}
__device__ __forceinline__ unsigned long long fma2(unsigned long long a, unsigned long long b, unsigned long long c) {
    unsigned long long r; asm("fma.rn.f32x2 %0, %1, %2, %3;" : "=l"(r) : "l"(a), "l"(b), "l"(c)); return r;
}

// ---------- cluster helpers ----------
__device__ __forceinline__ unsigned cta_rank() {
    unsigned r; asm("mov.u32 %0, %%cluster_ctarank;" : "=r"(r)); return r;
}
__device__ __forceinline__ void cluster_sync_all() {
    asm volatile("barrier.cluster.arrive.aligned;" ::: "memory");
    asm volatile("barrier.cluster.wait.aligned;" ::: "memory");
}
__device__ __forceinline__ unsigned mapa_addr(unsigned local_smem_addr, unsigned target_rank) {
    unsigned raddr;
    asm volatile("mapa.shared::cluster.u32 %0, %1, %2;" : "=r"(raddr)
                 : "r"(local_smem_addr), "r"(target_rank));
    return raddr;
}
__device__ __forceinline__ void st_cluster_relaxed_u64(unsigned remote_addr, unsigned long long v) {
    asm volatile("st.relaxed.cluster.shared::cluster.b64 [%0], %1;"
                 :: "r"(remote_addr), "l"(v) : "memory");
}
__device__ __forceinline__ unsigned long long ld_smem_volatile_u64(unsigned addr) {
    unsigned long long v;
    asm volatile("ld.volatile.shared.b64 %0, [%1];" : "=l"(v) : "r"(addr) : "memory");
    return v;
}

// =====================================================================================
// Kernel 1: exact FPS, 8-CTA cluster per cloud. Coords + d in registers. Per-iteration
// cross-CTA exchange: leader pushes one tagged 64-bit key per peer via relaxed DSMEM
// store; all threads spin on LOCAL smem slots until all 8 carry tag==m. No cluster
// barrier / mbarrier on the critical path. Key = [m:18 | d_bits:32 | (16383-idx):14];
// equal tags => u64 max == largest d, ties -> smallest index (matches jnp.argmax).
// =====================================================================================
__global__ __launch_bounds__(TFPS, 1) __cluster_dims__(GFPS, 1, 1)
void fps_kernel(const float* __restrict__ pos) {
    extern __shared__ float sh[];
    float* sx = sh;
    float* sy = sh + NP;
    float* sz = sh + 2*NP;
    __shared__ unsigned long long swarp[2][TFPS/32];
    __shared__ __align__(16) unsigned long long slot[2][GFPS];

    const int tid = threadIdx.x, lane = tid & 31, wid = tid >> 5;
    const unsigned rank = cta_rank();
    const int b = blockIdx.x / GFPS;
    const float* p = pos + (size_t)b * NP * 3;

    const unsigned slot_base = (unsigned)__cvta_generic_to_shared(&slot[0][0]);

    // init slots to an impossible tag (0x3FFFF)
    if (tid < 2*GFPS) slot[tid >> 3][tid & 7] = ~0ull;

    // stage full cloud coords (SoA) into smem — winner-coord broadcast lookups
    for (int i = tid; i < NP; i += TFPS) {
        sx[i] = p[3*i]; sy[i] = p[3*i+1]; sz[i] = p[3*i+2];
    }
    __syncthreads();
    cluster_sync_all();   // slots initialized + coords staged before any remote push

    // precompute remote slot addresses for this CTA's column (buf0; buf1 = +64B)
    unsigned raddr[GFPS];
#pragma unroll
    for (unsigned g = 0; g < GFPS; ++g)
        raddr[g] = mapa_addr(slot_base + rank * 8u, g);

    // own shard: coords + running min-distance in registers
    const int jbase = (int)rank * SHARD + tid;
    float mx[PPT], my[PPT], mz[PPT], d[PPT];
    const float x0 = sx[0], y0 = sy[0], z0 = sz[0];
    float bd = -FLT_MAX; int bj = 0;
#pragma unroll
    for (int k = 0; k < PPT; ++k) {
        int j = jbase + k*TFPS;
        mx[k] = sx[j]; my[k] = sy[j]; mz[k] = sz[j];
        float dx = __fsub_rn(mx[k], x0);
        float dy = __fsub_rn(my[k], y0);
        float dz = __fsub_rn(mz[k], z0);
        d[k] = __fadd_rn(__fadd_rn(__fmul_rn(dx,dx), __fmul_rn(dy,dy)), __fmul_rn(dz,dz));
        if (d[k] > bd) { bd = d[k]; bj = j; }
    }
    if (rank == 0 && tid == TFPS-1) {
        g_pc[((size_t)b*MM + 0)*3 + 0] = x0;
        g_pc[((size_t)b*MM + 0)*3 + 1] = y0;
        g_pc[((size_t)b*MM + 0)*3 + 2] = z0;
    }

    for (int m = 1; m < MM; ++m) {
        const int buf = m & 1;
        // --- key (untagged): d_bits<<14 | (16383 - idx), warp reduce ---
        unsigned long long key =
            ((unsigned long long)__float_as_uint(bd) << 14) | (unsigned)(16383 - bj);
#pragma unroll
        for (int o = 16; o > 0; o >>= 1) {
            unsigned long long v = __shfl_down_sync(0xffffffffu, key, o);
            if (v > key) key = v;
        }
        if (lane == 0) swarp[buf][wid] = key;
        __syncthreads();
        // --- CTA reduce (8 warps) + tagged push to all cluster CTAs ---
        if (wid == 0) {
            unsigned long long k2 = (lane < TFPS/32) ? swarp[buf][lane] : 0ull;
#pragma unroll
            for (int o = 4; o > 0; o >>= 1) {
                unsigned long long v = __shfl_down_sync(0xffffffffu, k2, o);
                if (v > k2) k2 = v;
            }
            if (lane == 0) {
                const unsigned long long tagged = ((unsigned long long)(unsigned)m << 46) | k2;
                const unsigned boff = (unsigned)buf * (GFPS * 8u);
#pragma unroll
                for (unsigned g = 0; g < GFPS; ++g)
                    st_cluster_relaxed_u64(raddr[g] + boff, tagged);
            }
        }
        // --- spin on local slots until all 8 carry tag == m ---
        const unsigned sb = slot_base + (unsigned)buf * (GFPS * 8u);
        unsigned long long kv[GFPS];
        const unsigned mt = (unsigned)m;
        for (;;) {
            bool ready = true;
#pragma unroll
            for (int g = 0; g < GFPS; ++g) {
                kv[g] = ld_smem_volatile_u64(sb + (unsigned)g * 8u);
                ready &= ((unsigned)(kv[g] >> 46) == mt);
            }
            if (ready) break;
        }
        // --- winner: 8-way max (equal tags, full-word compare is valid) ---
        unsigned long long w01 = kv[0] > kv[1] ? kv[0] : kv[1];
        unsigned long long w23 = kv[2] > kv[3] ? kv[2] : kv[3];
        unsigned long long w45 = kv[4] > kv[5] ? kv[4] : kv[5];
        unsigned long long w67 = kv[6] > kv[7] ? kv[6] : kv[7];
        unsigned long long w03 = w01 > w23 ? w01 : w23;
        unsigned long long w47 = w45 > w67 ? w45 : w67;
        unsigned long long w   = w03 > w47 ? w03 : w47;
        const int wj = 16383 - (int)(w & 0x3FFFull);
        const float wx = sx[wj], wy = sy[wj], wz = sz[wj];
        if (rank == 0 && tid == TFPS-1) {
            g_pc[((size_t)b*MM + m)*3 + 0] = wx;
            g_pc[((size_t)b*MM + m)*3 + 1] = wy;
            g_pc[((size_t)b*MM + m)*3 + 2] = wz;
        }
        // --- fused packed min-update + next argmax (exact op sequence) ---
        const unsigned long long nwx = pack2(-wx, -wx);
        const unsigned long long nwy = pack2(-wy, -wy);
        const unsigned long long nwz = pack2(-wz, -wz);
        bd = -FLT_MAX; bj = 0;
#pragma unroll
        for (int k = 0; k < PPT/2; ++k) {
            unsigned long long dx = add2(pack2(mx[2*k], mx[2*k+1]), nwx);
            unsigned long long dy = add2(pack2(my[2*k], my[2*k+1]), nwy);
            unsigned long long dz = add2(pack2(mz[2*k], mz[2*k+1]), nwz);
            unsigned long long s  = add2(add2(mul2(dx,dx), mul2(dy,dy)), mul2(dz,dz));
            float s0, s1; unpack2(s, s0, s1);
            d[2*k]   = fminf(d[2*k],   s0);
            d[2*k+1] = fminf(d[2*k+1], s1);
            if (d[2*k]   > bd) { bd = d[2*k];   bj = jbase + (2*k)*TFPS; }
            if (d[2*k+1] > bd) { bd = d[2*k+1]; bj = jbase + (2*k+1)*TFPS; }
        }
    }
    cluster_sync_all();   // keep CTAs resident until all exchanges consumed
}

// =====================================================================================
// Kernel 2: per-point layer-1 partials  u_j = x_j@W1[:32] + p_j@W1[32:35] + b1
// =====================================================================================
__global__ __launch_bounds__(256) void feat_kernel(const float* __restrict__ x,
                                                   const float* __restrict__ pos,
                                                   const float* __restrict__ W1,
                                                   const float* __restrict__ b1) {
    __shared__ float xs[4][FF];
    __shared__ float ps[4][3];
    const int j0 = blockIdx.x * 4;
    const int tid = threadIdx.x;
    if (tid < 128) xs[tid >> 5][tid & 31] = x[(size_t)(j0 + (tid >> 5))*FF + (tid & 31)];
    if (tid < 12)  ps[tid / 3][tid % 3]   = pos[(size_t)j0*3 + tid];
    __syncthreads();
    const int pt = tid >> 6, h = tid & 63;
    float acc = b1[h];
#pragma unroll
    for (int f = 0; f < FF; ++f) acc += xs[pt][f] * W1[f*HH + h];
    acc += ps[pt][0] * W1[32*HH + h];
    acc += ps[pt][1] * W1[33*HH + h];
    acc += ps[pt][2] * W1[34*HH + h];
    g_u[(size_t)(j0 + pt)*HH + h] = acc;
}

// =====================================================================================
// Kernel 3: ball query. Compact in-radius candidates; if cnt<=K emit directly (set
// semantics — downstream max-agg is order-invariant); else bitonic-sort next_pow2(cnt)
// packed (d2,idx) keys and take K smallest. Tie-break identical to stable top_k.
// =====================================================================================
__global__ __launch_bounds__(256) void ballq_kernel(const float* __restrict__ pos) {
    const float R2 = (float)(0.2 * 0.2);
    const int i = blockIdx.x;
    const int b = i / MM;
    __shared__ unsigned long long cand[CANDMAX];
    __shared__ int cnt;
    const int tid = threadIdx.x;
    if (tid == 0) cnt = 0;
    const float cx = g_pc[(size_t)i*3 + 0];
    const float cy = g_pc[(size_t)i*3 + 1];
    const float cz = g_pc[(size_t)i*3 + 2];
    __syncthreads();
    const float* p = pos + (size_t)b * NP * 3;
    for (int j = tid; j < NP; j += 256) {
        float dx = __fsub_rn(cx, p[3*j]);
        float dy = __fsub_rn(cy, p[3*j+1]);
        float dz = __fsub_rn(cz, p[3*j+2]);
        float d2 = __fadd_rn(__fadd_rn(__fmul_rn(dx,dx), __fmul_rn(dy,dy)), __fmul_rn(dz,dz));
        if (d2 <= R2) {
            int sl = atomicAdd(&cnt, 1);
            if (sl < CANDMAX)
                cand[sl] = ((unsigned long long)__float_as_uint(d2) << 32) | (unsigned)j;
        }
    }
    __syncthreads();
    const int c = min(cnt, CANDMAX);
    if (c > KK) {
        int p2 = KK;
        while (p2 < c) p2 <<= 1;
        for (int t = tid; t < p2; t += 256)
            if (t >= c) cand[t] = ~0ull;
        for (int k = 2; k <= p2; k <<= 1) {
            for (int s = k >> 1; s > 0; s >>= 1) {
                __syncthreads();
                for (int t = tid; t < p2; t += 256) {
                    int pr = t ^ s;
                    if (pr > t) {
                        unsigned long long a = cand[t], bv = cand[pr];
                        bool up = ((t & k) == 0);
                        if ((a > bv) == up) { cand[t] = bv; cand[pr] = a; }
                    }
                }
            }
        }
        __syncthreads();
    }
    const int v = min(c, KK);
    if (tid < KK) g_nbr[(size_t)i*KK + tid] = (tid < v) ? (int)(unsigned)cand[tid] : 0;
    if (tid == 0) g_cnt[i] = v;
}

// =====================================================================================
// Kernel 4: layer 2 + max aggregation
// =====================================================================================
__device__ __forceinline__ float dot64(const float* __restrict__ h1,
                                       const unsigned long long* __restrict__ w2p) {
    const float2* hb = (const float2*)h1;
    unsigned long long a0 = 0ull, a1 = 0ull;
#pragma unroll
    for (int h2 = 0; h2 < HH/2; h2 += 2) {
        float2 p0 = hb[h2], p1 = hb[h2 + 1];
        a0 = fma2(pack2(p0.x, p0.y), w2p[h2],     a0);
        a1 = fma2(pack2(p1.x, p1.y), w2p[h2 + 1], a1);
    }
    float l0, u0, l1, u1;
    unpack2(a0, l0, u0); unpack2(a1, l1, u1);
    return (l0 + u0) + (l1 + u1);
}

__global__ __launch_bounds__(128) void mlp_kernel(const float* __restrict__ W1,
                                                  const float* __restrict__ W2,
                                                  const float* __restrict__ b2,
                                                  float* __restrict__ out) {
    const int i = blockIdx.x;
    const int b = i / MM;
    const int tid = threadIdx.x;
    __shared__ float v[HH];
    __shared__ float h1buf[2][HH];

    unsigned long long w2p[HH/2];
#pragma unroll
    for (int h = 0; h < HH/2; ++h)
        w2p[h] = pack2(W2[(size_t)(2*h)*CO + tid], W2[(size_t)(2*h + 1)*CO + tid]);

    if (tid < HH) {
        float icx = __fdiv_rn(g_pc[(size_t)i*3 + 0], 0.2f);
        float icy = __fdiv_rn(g_pc[(size_t)i*3 + 1], 0.2f);
        float icz = __fdiv_rn(g_pc[(size_t)i*3 + 2], 0.2f);
        v[tid] = icx*W1[32*HH + tid] + icy*W1[33*HH + tid] + icz*W1[34*HH + tid];
    }
    const int cnt = g_cnt[i];
    float mx = -FLT_MAX;
    __syncthreads();

    const int which = tid >> 6, h = tid & 63;
    for (int jj = 0; jj < cnt; jj += 2) {
        int idx = jj + which;
        if (idx < cnt) {
            int nb = g_nbr[(size_t)i*KK + idx];
            h1buf[which][h] = fmaxf(g_u[((size_t)b*NP + nb)*HH + h] - v[h], 0.0f);
        }
        __syncthreads();
        mx = fmaxf(mx, dot64(h1buf[0], w2p));
        if (jj + 1 < cnt) mx = fmaxf(mx, dot64(h1buf[1], w2p));
        __syncthreads();
    }
    float res = (cnt > 0) ? (mx + b2[tid]) : 0.0f;
    out[(size_t)i*CO + tid] = res;
}

// =====================================================================================
// Kernel 5: tail outputs (centroid positions + batch vector)
// =====================================================================================
__global__ void tail_kernel(float* __restrict__ out, int has_pc, int has_batch) {
    const int i = blockIdx.x * 256 + threadIdx.x;
    if (has_pc && i < MTOT*3) out[(size_t)MTOT*CO + i] = g_pc[i];
    if (has_batch && i < MTOT) out[(size_t)MTOT*CO + (size_t)MTOT*3 + i] = (float)(i / MM);
}

extern "C" void kernel_launch(void* const* d_in, const int* in_sizes, int n_in,
                              void* d_out, int out_size) {
    const float* x   = (const float*)d_in[0];
    const float* pos = (const float*)d_in[1];
    const float* W1  = (const float*)d_in[3];
    const float* b1  = (const float*)d_in[4];
    const float* W2  = (const float*)d_in[5];
    const float* b2  = (const float*)d_in[6];
    float* out = (float*)d_out;

    cudaFuncSetAttribute(fps_kernel, cudaFuncAttributeMaxDynamicSharedMemorySize, 3*NP*4);

    fps_kernel<<<BB*GFPS, TFPS, 3*NP*4>>>(pos);
    feat_kernel<<<NTOT/4, 256>>>(x, pos, W1, b1);
    ballq_kernel<<<MTOT, 256>>>(pos);
    mlp_kernel<<<MTOT, 128>>>(W1, W2, b2, out);

    int has_pc    = out_size >= MTOT*CO + MTOT*3;
    int has_batch = out_size >= MTOT*CO + MTOT*3 + MTOT;
    if (has_pc)
        tail_kernel<<<(MTOT*3 + 255)/256, 256>>>(out, has_pc, has_batch);
}

// round 5
// speedup vs baseline: 3.1277x; 1.0405x over previous
#include <cuda_runtime.h>
#include <math.h>
#include <float.h>

#define BB   2
#define NP   16384
#define FF   32
#define MM   4096
#define KK   64
#define HH   64
#define CO   128
#define NTOT (BB*NP)
#define MTOT (BB*MM)
#define CANDMAX 2048

#define GFPS  8                 // CTAs per cloud (one cluster)
#define TFPS  256               // threads per FPS CTA
#define SHARD (NP/GFPS)         // 2048 points per CTA
#define PPT   (SHARD/TFPS)      // 8 points per thread

static __device__ float g_pc[MTOT*3];
static __device__ float g_u[NTOT*HH];
static __device__ int   g_nbr[MTOT*KK];
static __device__ int   g_cnt[MTOT];

// ---------- packed f32x2 helpers (lane-wise identical rounding to scalar fp32) ----------
__device__ __forceinline__ unsigned long long pack2(float lo, float hi) {
    unsigned long long r;
    asm("mov.b64 %0, {%1, %2};" : "=l"(r) : "r"(__float_as_uint(lo)), "r"(__float_as_uint(hi)));
    return r;
}
__device__ __forceinline__ void unpack2(unsigned long long v, float &lo, float &hi) {
    unsigned a, b;
    asm("mov.b64 {%0, %1}, %2;" : "=r"(a), "=r"(b) : "l"(v));
    lo = __uint_as_float(a); hi = __uint_as_float(b);
}
__device__ __forceinline__ unsigned long long add2(unsigned long long a, unsigned long long b) {
    unsigned long long r; asm("add.rn.f32x2 %0, %1, %2;" : "=l"(r) : "l"(a), "l"(b)); return r;
}
__device__ __forceinline__ unsigned long long mul2(unsigned long long a, unsigned long long b) {
    unsigned long long r; asm("mul.rn.f32x2 %0, %1, %2;" : "=l"(r) : "l"(a), "l"(b)); return r;
}
__device__ __forceinline__ unsigned long long fma2(unsigned long long a, unsigned long long b, unsigned long long c) {
    unsigned long long r; asm("fma.rn.f32x2 %0, %1, %2, %3;" : "=l"(r) : "l"(a), "l"(b), "l"(c)); return r;
}

// ---------- cluster / smem sync helpers ----------
__device__ __forceinline__ unsigned cta_rank() {
    unsigned r; asm("mov.u32 %0, %%cluster_ctarank;" : "=r"(r)); return r;
}
__device__ __forceinline__ void cluster_sync_all() {
    asm volatile("barrier.cluster.arrive.aligned;" ::: "memory");
    asm volatile("barrier.cluster.wait.aligned;" ::: "memory");
}
__device__ __forceinline__ unsigned mapa_addr(unsigned local_smem_addr, unsigned target_rank) {
    unsigned raddr;
    asm volatile("mapa.shared::cluster.u32 %0, %1, %2;" : "=r"(raddr)
                 : "r"(local_smem_addr), "r"(target_rank));
    return raddr;
}
__device__ __forceinline__ void st_cluster_relaxed_u64(unsigned remote_addr, unsigned long long v) {
    asm volatile("st.relaxed.cluster.shared::cluster.b64 [%0], %1;"
                 :: "r"(remote_addr), "l"(v) : "memory");
}
__device__ __forceinline__ unsigned long long ld_smem_volatile_u64(unsigned addr) {
    unsigned long long v;
    asm volatile("ld.volatile.shared.b64 %0, [%1];" : "=l"(v) : "r"(addr) : "memory");
    return v;
}
__device__ __forceinline__ void st_smem_volatile_u64(unsigned addr, unsigned long long v) {
    asm volatile("st.volatile.shared.b64 [%0], %1;" :: "r"(addr), "l"(v) : "memory");
}
__device__ __forceinline__ void ld_smem_volatile_v2(unsigned addr,
                                                    unsigned long long &a, unsigned long long &b) {
    asm volatile("ld.volatile.shared.v2.u64 {%0, %1}, [%2];"
                 : "=l"(a), "=l"(b) : "r"(addr) : "memory");
}

// =====================================================================================
// Kernel 1: exact FPS, 8-CTA cluster per cloud. Coords + d in registers.
//   warp reduce:   redux.sync max on d-bits (u32 compare valid: d>=0) + redux.sync min
//                  on index among tied lanes (== jnp.argmax smallest-index tie-break).
//   CTA reduce:    warp leaders st.volatile tagged keys -> swarp[buf][wid]; warp0 polls
//                  tags (no __syncthreads), 8-way max, lane0 pushes to all cluster CTAs.
//   cluster xchg:  relaxed DSMEM stores into per-CTA tagged slots; all threads spin on
//                  LOCAL smem until all 8 slots carry tag==m.
// Key = [m:18 | d_bits:32 | (16383-idx):14]; equal tags => u64 max == largest d,
// ties -> smallest index. Double-buffered swarp/slots; warp0/leader is the per-CTA
// serialization point so no writer can lap a reader on the same buffer.
// =====================================================================================
__global__ __launch_bounds__(TFPS, 1) __cluster_dims__(GFPS, 1, 1)
void fps_kernel(const float* __restrict__ pos) {
    extern __shared__ float sh[];
    float* sx = sh;
    float* sy = sh + NP;
    float* sz = sh + 2*NP;
    __shared__ __align__(16) unsigned long long swarp[2][TFPS/32];
    __shared__ __align__(16) unsigned long long slot[2][GFPS];

    const int tid = threadIdx.x, lane = tid & 31, wid = tid >> 5;
    const unsigned rank = cta_rank();
    const int b = blockIdx.x / GFPS;
    const float* p = pos + (size_t)b * NP * 3;

    const unsigned slot_base  = (unsigned)__cvta_generic_to_shared(&slot[0][0]);
    const unsigned swarp_base = (unsigned)__cvta_generic_to_shared(&swarp[0][0]);

    // init slots + swarp to impossible tags
    if (tid < 2*GFPS) slot[tid >> 3][tid & 7] = ~0ull;
    if (tid < 16)     swarp[tid >> 3][tid & 7] = ~0ull;

    // stage full cloud coords (SoA) into smem — winner-coord broadcast lookups
    for (int i = tid; i < NP; i += TFPS) {
        sx[i] = p[3*i]; sy[i] = p[3*i+1]; sz[i] = p[3*i+2];
    }
    __syncthreads();
    cluster_sync_all();   // slots initialized + coords staged before any remote push

    // precompute remote slot addresses for this CTA's column (buf0; buf1 = +64B)
    unsigned raddr[GFPS];
#pragma unroll
    for (unsigned g = 0; g < GFPS; ++g)
        raddr[g] = mapa_addr(slot_base + rank * 8u, g);

    // own shard: coords + running min-distance in registers
    const int jbase = (int)rank * SHARD + tid;
    float mx[PPT], my[PPT], mz[PPT], d[PPT];
    const float x0 = sx[0], y0 = sy[0], z0 = sz[0];
    float bd = -FLT_MAX; int bj = 0;
#pragma unroll
    for (int k = 0; k < PPT; ++k) {
        int j = jbase + k*TFPS;
        mx[k] = sx[j]; my[k] = sy[j]; mz[k] = sz[j];
        float dx = __fsub_rn(mx[k], x0);
        float dy = __fsub_rn(my[k], y0);
        float dz = __fsub_rn(mz[k], z0);
        d[k] = __fadd_rn(__fadd_rn(__fmul_rn(dx,dx), __fmul_rn(dy,dy)), __fmul_rn(dz,dz));
        if (d[k] > bd) { bd = d[k]; bj = j; }
    }
    if (rank == 0 && tid == TFPS-1) {
        g_pc[((size_t)b*MM + 0)*3 + 0] = x0;
        g_pc[((size_t)b*MM + 0)*3 + 1] = y0;
        g_pc[((size_t)b*MM + 0)*3 + 2] = z0;
    }

    for (int m = 1; m < MM; ++m) {
        const int buf = m & 1;
        const unsigned mt = (unsigned)m;
        // --- warp reduce via redux: max d-bits, then min index among tied lanes ---
        const unsigned mb   = __float_as_uint(bd);        // bd >= 0 => u32 order == f32 order
        const unsigned wmax = __reduce_max_sync(0xffffffffu, mb);
        const unsigned candi = (mb == wmax) ? (unsigned)bj : 0xFFFFFFFFu;
        const unsigned widx  = __reduce_min_sync(0xffffffffu, candi);
        if (lane == 0) {
            const unsigned long long tk =
                ((unsigned long long)mt << 46) |
                ((unsigned long long)wmax << 14) | (unsigned)(16383 - widx);
            st_smem_volatile_u64(swarp_base + (unsigned)(buf*(TFPS/32) + wid) * 8u, tk);
        }
        // --- warp0: poll 8 tagged warp-winners (no bar.sync), 8-way max, push ---
        if (wid == 0) {
            const unsigned sa = swarp_base + (unsigned)buf * ((TFPS/32) * 8u);
            unsigned long long t0,t1,t2,t3,t4,t5,t6,t7;
            for (;;) {
                ld_smem_volatile_v2(sa,      t0, t1);
                ld_smem_volatile_v2(sa + 16, t2, t3);
                ld_smem_volatile_v2(sa + 32, t4, t5);
                ld_smem_volatile_v2(sa + 48, t6, t7);
                bool ok = ((unsigned)(t0 >> 46) == mt) & ((unsigned)(t1 >> 46) == mt)
                        & ((unsigned)(t2 >> 46) == mt) & ((unsigned)(t3 >> 46) == mt)
                        & ((unsigned)(t4 >> 46) == mt) & ((unsigned)(t5 >> 46) == mt)
                        & ((unsigned)(t6 >> 46) == mt) & ((unsigned)(t7 >> 46) == mt);
                if (ok) break;
            }
            unsigned long long a01 = t0 > t1 ? t0 : t1;
            unsigned long long a23 = t2 > t3 ? t2 : t3;
            unsigned long long a45 = t4 > t5 ? t4 : t5;
            unsigned long long a67 = t6 > t7 ? t6 : t7;
            unsigned long long a03 = a01 > a23 ? a01 : a23;
            unsigned long long a47 = a45 > a67 ? a45 : a67;
            unsigned long long ak  = a03 > a47 ? a03 : a47;   // tagged m already
            if (lane == 0) {
                const unsigned boff = (unsigned)buf * (GFPS * 8u);
#pragma unroll
                for (unsigned g = 0; g < GFPS; ++g)
                    st_cluster_relaxed_u64(raddr[g] + boff, ak);
            }
        }
        // --- spin on local slots until all 8 carry tag == m ---
        const unsigned sb = slot_base + (unsigned)buf * (GFPS * 8u);
        unsigned long long kv[GFPS];
        for (;;) {
            bool ready = true;
#pragma unroll
            for (int g = 0; g < GFPS; g += 2) {
                ld_smem_volatile_v2(sb + (unsigned)g * 8u, kv[g], kv[g+1]);
                ready &= ((unsigned)(kv[g]   >> 46) == mt);
                ready &= ((unsigned)(kv[g+1] >> 46) == mt);
            }
            if (ready) break;
        }
        // --- winner: 8-way max (equal tags, full-word compare is valid) ---
        unsigned long long w01 = kv[0] > kv[1] ? kv[0] : kv[1];
        unsigned long long w23 = kv[2] > kv[3] ? kv[2] : kv[3];
        unsigned long long w45 = kv[4] > kv[5] ? kv[4] : kv[5];
        unsigned long long w67 = kv[6] > kv[7] ? kv[6] : kv[7];
        unsigned long long w03 = w01 > w23 ? w01 : w23;
        unsigned long long w47 = w45 > w67 ? w45 : w67;
        unsigned long long w   = w03 > w47 ? w03 : w47;
        const int wj = 16383 - (int)(w & 0x3FFFull);
        const float wx = sx[wj], wy = sy[wj], wz = sz[wj];
        if (rank == 0 && tid == TFPS-1) {
            g_pc[((size_t)b*MM + m)*3 + 0] = wx;
            g_pc[((size_t)b*MM + m)*3 + 1] = wy;
            g_pc[((size_t)b*MM + m)*3 + 2] = wz;
        }
        // --- fused packed min-update + next argmax (exact op sequence) ---
        const unsigned long long nwx = pack2(-wx, -wx);
        const unsigned long long nwy = pack2(-wy, -wy);
        const unsigned long long nwz = pack2(-wz, -wz);
        bd = -FLT_MAX; bj = 0;
#pragma unroll
        for (int k = 0; k < PPT/2; ++k) {
            unsigned long long dx = add2(pack2(mx[2*k], mx[2*k+1]), nwx);
            unsigned long long dy = add2(pack2(my[2*k], my[2*k+1]), nwy);
            unsigned long long dz = add2(pack2(mz[2*k], mz[2*k+1]), nwz);
            unsigned long long s  = add2(add2(mul2(dx,dx), mul2(dy,dy)), mul2(dz,dz));
            float s0, s1; unpack2(s, s0, s1);
            d[2*k]   = fminf(d[2*k],   s0);
            d[2*k+1] = fminf(d[2*k+1], s1);
            if (d[2*k]   > bd) { bd = d[2*k];   bj = jbase + (2*k)*TFPS; }
            if (d[2*k+1] > bd) { bd = d[2*k+1]; bj = jbase + (2*k+1)*TFPS; }
        }
    }
    cluster_sync_all();   // keep CTAs resident until all exchanges consumed
}

// =====================================================================================
// Kernel 2: per-point layer-1 partials  u_j = x_j@W1[:32] + p_j@W1[32:35] + b1
// =====================================================================================
__global__ __launch_bounds__(256) void feat_kernel(const float* __restrict__ x,
                                                   const float* __restrict__ pos,
                                                   const float* __restrict__ W1,
                                                   const float* __restrict__ b1) {
    __shared__ float xs[4][FF];
    __shared__ float ps[4][3];
    const int j0 = blockIdx.x * 4;
    const int tid = threadIdx.x;
    if (tid < 128) xs[tid >> 5][tid & 31] = x[(size_t)(j0 + (tid >> 5))*FF + (tid & 31)];
    if (tid < 12)  ps[tid / 3][tid % 3]   = pos[(size_t)j0*3 + tid];
    __syncthreads();
    const int pt = tid >> 6, h = tid & 63;
    float acc = b1[h];
#pragma unroll
    for (int f = 0; f < FF; ++f) acc += xs[pt][f] * W1[f*HH + h];
    acc += ps[pt][0] * W1[32*HH + h];
    acc += ps[pt][1] * W1[33*HH + h];
    acc += ps[pt][2] * W1[34*HH + h];
    g_u[(size_t)(j0 + pt)*HH + h] = acc;
}

// =====================================================================================
// Kernel 3: ball query. Compact in-radius candidates; if cnt<=K emit directly (set
// semantics — downstream max-agg is order-invariant); else bitonic-sort next_pow2(cnt)
// packed (d2,idx) keys and take K smallest. Tie-break identical to stable top_k.
// =====================================================================================
__global__ __launch_bounds__(256) void ballq_kernel(const float* __restrict__ pos) {
    const float R2 = (float)(0.2 * 0.2);
    const int i = blockIdx.x;
    const int b = i / MM;
    __shared__ unsigned long long cand[CANDMAX];
    __shared__ int cnt;
    const int tid = threadIdx.x;
    if (tid == 0) cnt = 0;
    const float cx = g_pc[(size_t)i*3 + 0];
    const float cy = g_pc[(size_t)i*3 + 1];
    const float cz = g_pc[(size_t)i*3 + 2];
    __syncthreads();
    const float* p = pos + (size_t)b * NP * 3;
    for (int j = tid; j < NP; j += 256) {
        float dx = __fsub_rn(cx, p[3*j]);
        float dy = __fsub_rn(cy, p[3*j+1]);
        float dz = __fsub_rn(cz, p[3*j+2]);
        float d2 = __fadd_rn(__fadd_rn(__fmul_rn(dx,dx), __fmul_rn(dy,dy)), __fmul_rn(dz,dz));
        if (d2 <= R2) {
            int sl = atomicAdd(&cnt, 1);
            if (sl < CANDMAX)
                cand[sl] = ((unsigned long long)__float_as_uint(d2) << 32) | (unsigned)j;
        }
    }
    __syncthreads();
    const int c = min(cnt, CANDMAX);
    if (c > KK) {
        int p2 = KK;
        while (p2 < c) p2 <<= 1;
        for (int t = tid; t < p2; t += 256)
            if (t >= c) cand[t] = ~0ull;
        for (int k = 2; k <= p2; k <<= 1) {
            for (int s = k >> 1; s > 0; s >>= 1) {
                __syncthreads();
                for (int t = tid; t < p2; t += 256) {
                    int pr = t ^ s;
                    if (pr > t) {
                        unsigned long long a = cand[t], bv = cand[pr];
                        bool up = ((t & k) == 0);
                        if ((a > bv) == up) { cand[t] = bv; cand[pr] = a; }
                    }
                }
            }
        }
        __syncthreads();
    }
    const int v = min(c, KK);
    if (tid < KK) g_nbr[(size_t)i*KK + tid] = (tid < v) ? (int)(unsigned)cand[tid] : 0;
    if (tid == 0) g_cnt[i] = v;
}

// =====================================================================================
// Kernel 4: layer 2 + max aggregation
// =====================================================================================
__device__ __forceinline__ float dot64(const float* __restrict__ h1,
                                       const unsigned long long* __restrict__ w2p) {
    const float2* hb = (const float2*)h1;
    unsigned long long a0 = 0ull, a1 = 0ull;
#pragma unroll
    for (int h2 = 0; h2 < HH/2; h2 += 2) {
        float2 p0 = hb[h2], p1 = hb[h2 + 1];
        a0 = fma2(pack2(p0.x, p0.y), w2p[h2],     a0);
        a1 = fma2(pack2(p1.x, p1.y), w2p[h2 + 1], a1);
    }
    float l0, u0, l1, u1;
    unpack2(a0, l0, u0); unpack2(a1, l1, u1);
    return (l0 + u0) + (l1 + u1);
}

__global__ __launch_bounds__(128) void mlp_kernel(const float* __restrict__ W1,
                                                  const float* __restrict__ W2,
                                                  const float* __restrict__ b2,
                                                  float* __restrict__ out) {
    const int i = blockIdx.x;
    const int b = i / MM;
    const int tid = threadIdx.x;
    __shared__ float v[HH];
    __shared__ float h1buf[2][HH];

    unsigned long long w2p[HH/2];
#pragma unroll
    for (int h = 0; h < HH/2; ++h)
        w2p[h] = pack2(W2[(size_t)(2*h)*CO + tid], W2[(size_t)(2*h + 1)*CO + tid]);

    if (tid < HH) {
        float icx = __fdiv_rn(g_pc[(size_t)i*3 + 0], 0.2f);
        float icy = __fdiv_rn(g_pc[(size_t)i*3 + 1], 0.2f);
        float icz = __fdiv_rn(g_pc[(size_t)i*3 + 2], 0.2f);
        v[tid] = icx*W1[32*HH + tid] + icy*W1[33*HH + tid] + icz*W1[34*HH + tid];
    }
    const int cnt = g_cnt[i];
    float mx = -FLT_MAX;
    __syncthreads();

    const int which = tid >> 6, h = tid & 63;
    for (int jj = 0; jj < cnt; jj += 2) {
        int idx = jj + which;
        if (idx < cnt) {
            int nb = g_nbr[(size_t)i*KK + idx];
            h1buf[which][h] = fmaxf(g_u[((size_t)b*NP + nb)*HH + h] - v[h], 0.0f);
        }
        __syncthreads();
        mx = fmaxf(mx, dot64(h1buf[0], w2p));
        if (jj + 1 < cnt) mx = fmaxf(mx, dot64(h1buf[1], w2p));
        __syncthreads();
    }
    float res = (cnt > 0) ? (mx + b2[tid]) : 0.0f;
    out[(size_t)i*CO + tid] = res;
}

// =====================================================================================
// Kernel 5: tail outputs (centroid positions + batch vector)
// =====================================================================================
__global__ void tail_kernel(float* __restrict__ out, int has_pc, int has_batch) {
    const int i = blockIdx.x * 256 + threadIdx.x;
    if (has_pc && i < MTOT*3) out[(size_t)MTOT*CO + i] = g_pc[i];
    if (has_batch && i < MTOT) out[(size_t)MTOT*CO + (size_t)MTOT*3 + i] = (float)(i / MM);
}

extern "C" void kernel_launch(void* const* d_in, const int* in_sizes, int n_in,
                              void* d_out, int out_size) {
    const float* x   = (const float*)d_in[0];
    const float* pos = (const float*)d_in[1];
    const float* W1  = (const float*)d_in[3];
    const float* b1  = (const float*)d_in[4];
    const float* W2  = (const float*)d_in[5];
    const float* b2  = (const float*)d_in[6];
    float* out = (float*)d_out;

    cudaFuncSetAttribute(fps_kernel, cudaFuncAttributeMaxDynamicSharedMemorySize, 3*NP*4);

    fps_kernel<<<BB*GFPS, TFPS, 3*NP*4>>>(pos);
    feat_kernel<<<NTOT/4, 256>>>(x, pos, W1, b1);
    ballq_kernel<<<MTOT, 256>>>(pos);
    mlp_kernel<<<MTOT, 128>>>(W1, W2, b2, out);

    int has_pc    = out_size >= MTOT*CO + MTOT*3;
    int has_batch = out_size >= MTOT*CO + MTOT*3 + MTOT;
    if (has_pc)
        tail_kernel<<<(MTOT*3 + 255)/256, 256>>>(out, has_pc, has_batch);
}

// round 6
// speedup vs baseline: 3.6380x; 1.1632x over previous
#include <cuda_runtime.h>
#include <math.h>
#include <float.h>

#define BB   2
#define NP   16384
#define FF   32
#define MM   4096
#define KK   64
#define HH   64
#define CO   128
#define NTOT (BB*NP)
#define MTOT (BB*MM)
#define CANDMAX 2048
#define NBIN 2048

#define GFPS  8                 // CTAs per cloud (one cluster)
#define CWARPS 8                // compute warps per CTA
#define TFPS  (CWARPS*32 + 32)  // + 1 dedicated comms warp = 288
#define CTHR  (CWARPS*32)       // 256 compute threads
#define SHARD (NP/GFPS)         // 2048 points per CTA
#define PPT   (SHARD/CTHR)      // 8 points per thread

static __device__ float g_pc[MTOT*3];
static __device__ float g_u[NTOT*HH];
static __device__ int   g_nbr[MTOT*KK];
static __device__ int   g_cnt[MTOT];

// ---------- packed f32x2 helpers (lane-wise identical rounding to scalar fp32) ----------
__device__ __forceinline__ unsigned long long pack2(float lo, float hi) {
    unsigned long long r;
    asm("mov.b64 %0, {%1, %2};" : "=l"(r) : "r"(__float_as_uint(lo)), "r"(__float_as_uint(hi)));
    return r;
}
__device__ __forceinline__ void unpack2(unsigned long long v, float &lo, float &hi) {
    unsigned a, b;
    asm("mov.b64 {%0, %1}, %2;" : "=r"(a), "=r"(b) : "l"(v));
    lo = __uint_as_float(a); hi = __uint_as_float(b);
}
__device__ __forceinline__ unsigned long long add2(unsigned long long a, unsigned long long b) {
    unsigned long long r; asm("add.rn.f32x2 %0, %1, %2;" : "=l"(r) : "l"(a), "l"(b)); return r;
}
__device__ __forceinline__ unsigned long long mul2(unsigned long long a, unsigned long long b) {
    unsigned long long r; asm("mul.rn.f32x2 %0, %1, %2;" : "=l"(r) : "l"(a), "l"(b)); return r;
}
__device__ __forceinline__ unsigned long long fma2(unsigned long long a, unsigned long long b, unsigned long long c) {
    unsigned long long r; asm("fma.rn.f32x2 %0, %1, %2, %3;" : "=l"(r) : "l"(a), "l"(b), "l"(c)); return r;
}

// ---------- cluster / smem sync helpers ----------
__device__ __forceinline__ unsigned cta_rank() {
    unsigned r; asm("mov.u32 %0, %%cluster_ctarank;" : "=r"(r)); return r;
}
__device__ __forceinline__ void cluster_sync_all() {
    asm volatile("barrier.cluster.arrive.aligned;" ::: "memory");
    asm volatile("barrier.cluster.wait.aligned;" ::: "memory");
}
__device__ __forceinline__ unsigned mapa_addr(unsigned local_smem_addr, unsigned target_rank) {
    unsigned raddr;
    asm volatile("mapa.shared::cluster.u32 %0, %1, %2;" : "=r"(raddr)
                 : "r"(local_smem_addr), "r"(target_rank));
    return raddr;
}
__device__ __forceinline__ void st_cluster_relaxed_u64(unsigned remote_addr, unsigned long long v) {
    asm volatile("st.relaxed.cluster.shared::cluster.b64 [%0], %1;"
                 :: "r"(remote_addr), "l"(v) : "memory");
}
__device__ __forceinline__ unsigned long long ld_smem_volatile_u64(unsigned addr) {
    unsigned long long v;
    asm volatile("ld.volatile.shared.b64 %0, [%1];" : "=l"(v) : "r"(addr) : "memory");
    return v;
}
__device__ __forceinline__ void st_smem_volatile_u64(unsigned addr, unsigned long long v) {
    asm volatile("st.volatile.shared.b64 [%0], %1;" :: "r"(addr), "l"(v) : "memory");
}
__device__ __forceinline__ void ld_smem_volatile_v2(unsigned addr,
                                                    unsigned long long &a, unsigned long long &b) {
    asm volatile("ld.volatile.shared.v2.u64 {%0, %1}, [%2];"
                 : "=l"(a), "=l"(b) : "r"(addr) : "memory");
}

// =====================================================================================
// Kernel 1: exact FPS, 8-CTA cluster per cloud, 8 compute warps + 1 comms warp per CTA.
//   compute warps: fused packed min-update + argmax; redux(max d-bits)+redux(min idx on
//                  ties); leader pushes tagged warp-winner DIRECTLY to all 8 CTAs'
//                  slot[buf][rank][wid] (64 slots/buf); then spins on local bulletin.
//   comms warp:    polls the 64 local slots (1 v2.u64 per lane), split-redux winner
//                  (max d, min idx among ties), publishes tagged bulletin; rank0 lane0
//                  writes g_pc.
// Tag/lap safety: writers reach buffer b at iter m+2 only after passing bulletin m+1,
// which comms publishes only after consuming slots m+1, which needs all compute warps
// (warp-synchronous spins) past bulletin m. All selection math bit-exact vs reference.
// =====================================================================================
__global__ __launch_bounds__(TFPS, 1) __cluster_dims__(GFPS, 1, 1)
void fps_kernel(const float* __restrict__ pos) {
    extern __shared__ float sh[];
    float* sx = sh;
    float* sy = sh + NP;
    float* sz = sh + 2*NP;
    __shared__ __align__(16) unsigned long long slot[2][GFPS*CWARPS];  // [buf][src*8+warp]
    __shared__ __align__(16) unsigned long long bull[2];

    const int tid = threadIdx.x, lane = tid & 31, wid = tid >> 5;
    const unsigned rank = cta_rank();
    const int b = blockIdx.x / GFPS;
    const float* p = pos + (size_t)b * NP * 3;

    const unsigned slot_base = (unsigned)__cvta_generic_to_shared(&slot[0][0]);
    const unsigned bull_base = (unsigned)__cvta_generic_to_shared(&bull[0]);

    // init slots + bulletin to impossible tags
    for (int t = tid; t < 2*GFPS*CWARPS; t += TFPS) slot[t >> 6][t & 63] = ~0ull;
    if (tid == 0) { bull[0] = ~0ull; bull[1] = ~0ull; }

    // stage full cloud coords (SoA) into smem
    for (int i = tid; i < NP; i += TFPS) {
        sx[i] = p[3*i]; sy[i] = p[3*i+1]; sz[i] = p[3*i+2];
    }
    __syncthreads();
    cluster_sync_all();   // slots/bulletin initialized + coords staged everywhere

    if (wid < CWARPS) {
        // ================= compute warps =================
        unsigned raddr[GFPS];
#pragma unroll
        for (unsigned g = 0; g < GFPS; ++g)
            raddr[g] = mapa_addr(slot_base + (rank*CWARPS + (unsigned)wid)*8u, g);

        const int jbase = (int)rank * SHARD + tid;   // tid < 256 here
        float mx[PPT], my[PPT], mz[PPT], d[PPT];
        const float x0 = sx[0], y0 = sy[0], z0 = sz[0];
        float bd = -FLT_MAX; int bj = 0;
#pragma unroll
        for (int k = 0; k < PPT; ++k) {
            int j = jbase + k*CTHR;
            mx[k] = sx[j]; my[k] = sy[j]; mz[k] = sz[j];
            float dx = __fsub_rn(mx[k], x0);
            float dy = __fsub_rn(my[k], y0);
            float dz = __fsub_rn(mz[k], z0);
            d[k] = __fadd_rn(__fadd_rn(__fmul_rn(dx,dx), __fmul_rn(dy,dy)), __fmul_rn(dz,dz));
            if (d[k] > bd) { bd = d[k]; bj = j; }
        }

        for (int m = 1; m < MM; ++m) {
            const int buf = m & 1;
            const unsigned mt = (unsigned)m;
            // warp reduce: max d-bits (u32 order valid, d>=0), min idx among ties
            const unsigned mb   = __float_as_uint(bd);
            const unsigned wmax = __reduce_max_sync(0xffffffffu, mb);
            const unsigned ci   = (mb == wmax) ? (unsigned)bj : 0xFFFFFFFFu;
            const unsigned widx = __reduce_min_sync(0xffffffffu, ci);
            if (lane == 0) {
                const unsigned long long key =
                    ((unsigned long long)mt << 46) |
                    ((unsigned long long)wmax << 14) | widx;
                const unsigned boff = (unsigned)buf * (GFPS*CWARPS*8u);
#pragma unroll
                for (unsigned g = 0; g < GFPS; ++g)
                    st_cluster_relaxed_u64(raddr[g] + boff, key);
            }
            // spin on local bulletin
            const unsigned ba = bull_base + (unsigned)buf * 8u;
            unsigned long long k;
            do { k = ld_smem_volatile_u64(ba); } while ((unsigned)(k >> 46) != mt);
            const int wj = (int)(k & 0x3FFFull);
            const float wx = sx[wj], wy = sy[wj], wz = sz[wj];
            // fused packed min-update + next argmax (exact op sequence)
            const unsigned long long nwx = pack2(-wx, -wx);
            const unsigned long long nwy = pack2(-wy, -wy);
            const unsigned long long nwz = pack2(-wz, -wz);
            bd = -FLT_MAX; bj = 0;
#pragma unroll
            for (int kk = 0; kk < PPT/2; ++kk) {
                unsigned long long dx = add2(pack2(mx[2*kk], mx[2*kk+1]), nwx);
                unsigned long long dy = add2(pack2(my[2*kk], my[2*kk+1]), nwy);
                unsigned long long dz = add2(pack2(mz[2*kk], mz[2*kk+1]), nwz);
                unsigned long long s  = add2(add2(mul2(dx,dx), mul2(dy,dy)), mul2(dz,dz));
                float s0, s1; unpack2(s, s0, s1);
                d[2*kk]   = fminf(d[2*kk],   s0);
                d[2*kk+1] = fminf(d[2*kk+1], s1);
                if (d[2*kk]   > bd) { bd = d[2*kk];   bj = jbase + (2*kk)*CTHR; }
                if (d[2*kk+1] > bd) { bd = d[2*kk+1]; bj = jbase + (2*kk+1)*CTHR; }
            }
        }
    } else {
        // ================= comms warp =================
        if (rank == 0 && lane == 0) {
            g_pc[((size_t)b*MM + 0)*3 + 0] = sx[0];
            g_pc[((size_t)b*MM + 0)*3 + 1] = sy[0];
            g_pc[((size_t)b*MM + 0)*3 + 2] = sz[0];
        }
        for (int m = 1; m < MM; ++m) {
            const int buf = m & 1;
            const unsigned mt = (unsigned)m;
            const unsigned sa = slot_base + (unsigned)buf * (GFPS*CWARPS*8u) + (unsigned)lane*16u;
            unsigned long long k0, k1;
            for (;;) {
                ld_smem_volatile_v2(sa, k0, k1);
                bool ok = ((unsigned)(k0 >> 46) == mt) & ((unsigned)(k1 >> 46) == mt);
                if (__all_sync(0xffffffffu, ok)) break;
            }
            // lane-local best of its 2 slots: larger d, then smaller idx
            const unsigned d0 = (unsigned)(k0 >> 14), d1 = (unsigned)(k1 >> 14);
            const unsigned i0 = (unsigned)(k0 & 0x3FFFull), i1 = (unsigned)(k1 & 0x3FFFull);
            unsigned dl, il;
            if (d0 > d1)      { dl = d0; il = i0; }
            else if (d1 > d0) { dl = d1; il = i1; }
            else              { dl = d0; il = min(i0, i1); }
            const unsigned wd = __reduce_max_sync(0xffffffffu, dl);
            const unsigned ci = (dl == wd) ? il : 0xFFFFFFFFu;
            const unsigned wi = __reduce_min_sync(0xffffffffu, ci);
            if (lane == 0) {
                const unsigned long long bkey =
                    ((unsigned long long)mt << 46) | ((unsigned long long)wd << 14) | wi;
                st_smem_volatile_u64(bull_base + (unsigned)buf * 8u, bkey);
                if (rank == 0) {
                    g_pc[((size_t)b*MM + m)*3 + 0] = sx[wi];
                    g_pc[((size_t)b*MM + m)*3 + 1] = sy[wi];
                    g_pc[((size_t)b*MM + m)*3 + 2] = sz[wi];
                }
            }
        }
    }
    cluster_sync_all();   // keep CTAs resident until all exchanges consumed
}

// =====================================================================================
// Kernel 2: per-point layer-1 partials  u_j = x_j@W1[:32] + p_j@W1[32:35] + b1
// =====================================================================================
__global__ __launch_bounds__(256) void feat_kernel(const float* __restrict__ x,
                                                   const float* __restrict__ pos,
                                                   const float* __restrict__ W1,
                                                   const float* __restrict__ b1) {
    __shared__ float xs[4][FF];
    __shared__ float ps[4][3];
    const int j0 = blockIdx.x * 4;
    const int tid = threadIdx.x;
    if (tid < 128) xs[tid >> 5][tid & 31] = x[(size_t)(j0 + (tid >> 5))*FF + (tid & 31)];
    if (tid < 12)  ps[tid / 3][tid % 3]   = pos[(size_t)j0*3 + tid];
    __syncthreads();
    const int pt = tid >> 6, h = tid & 63;
    float acc = b1[h];
#pragma unroll
    for (int f = 0; f < FF; ++f) acc += xs[pt][f] * W1[f*HH + h];
    acc += ps[pt][0] * W1[32*HH + h];
    acc += ps[pt][1] * W1[33*HH + h];
    acc += ps[pt][2] * W1[34*HH + h];
    g_u[(size_t)(j0 + pt)*HH + h] = acc;
}

// =====================================================================================
// Kernel 3: ball query with radix-select top-K.
//   1) compact in-radius candidates (key [d2:32|idx:32]);
//   2) c<=K: emit all (order-invariant downstream);
//   3) else histogram top-11 float bits of d2 (monotone), CTA scan -> threshold bin T
//      containing the K-th element; emit all bin<T directly; bitonic-sort only bin==T
//      by full (d2,idx) key and emit the (K - nless) smallest. Exact same SET as the
//      reference's stable top_k. Fallback to full sort if threshold bin > 256 keys.
// =====================================================================================
__global__ __launch_bounds__(256) void ballq_kernel(const float* __restrict__ pos) {
    const float R2 = (float)(0.2 * 0.2);
    const int i = blockIdx.x;
    const int b = i / MM;
    __shared__ unsigned long long cand[CANDMAX];
    __shared__ int hist[NBIN];
    __shared__ unsigned long long tbuf[256];
    __shared__ int cnt, outc, tcnt, tsel_s, nless_s;
    __shared__ int wsum[8];
    const int tid = threadIdx.x;
    const int lane = tid & 31, w = tid >> 5;
    if (tid == 0) { cnt = 0; outc = 0; tcnt = 0; }
    const float cx = g_pc[(size_t)i*3 + 0];
    const float cy = g_pc[(size_t)i*3 + 1];
    const float cz = g_pc[(size_t)i*3 + 2];
    for (int t = tid; t < NBIN; t += 256) hist[t] = 0;
    __syncthreads();
    const float* p = pos + (size_t)b * NP * 3;
    for (int j = tid; j < NP; j += 256) {
        float dx = __fsub_rn(cx, p[3*j]);
        float dy = __fsub_rn(cy, p[3*j+1]);
        float dz = __fsub_rn(cz, p[3*j+2]);
        float d2 = __fadd_rn(__fadd_rn(__fmul_rn(dx,dx), __fmul_rn(dy,dy)), __fmul_rn(dz,dz));
        if (d2 <= R2) {
            int sl = atomicAdd(&cnt, 1);
            if (sl < CANDMAX)
                cand[sl] = ((unsigned long long)__float_as_uint(d2) << 32) | (unsigned)j;
        }
    }
    __syncthreads();
    const int c = min(cnt, CANDMAX);

    if (c <= KK) {
        for (int s = tid; s < c; s += 256)
            g_nbr[(size_t)i*KK + s] = (int)(unsigned)cand[s];
        if (tid == 0) g_cnt[i] = c;
        return;
    }

    // histogram on top-11 bits of d2 (bits 63..53 of the key)
    for (int s = tid; s < c; s += 256)
        atomicAdd(&hist[(unsigned)(cand[s] >> 53)], 1);
    __syncthreads();

    // CTA scan over 2048 bins (8 per thread) to locate threshold bin
    const int base = tid * 8;
    int h[8]; int ssum = 0;
#pragma unroll
    for (int q = 0; q < 8; ++q) { h[q] = hist[base + q]; ssum += h[q]; }
    int v = ssum;
#pragma unroll
    for (int o = 1; o < 32; o <<= 1) {
        int n = __shfl_up_sync(0xffffffffu, v, o);
        if (lane >= o) v += n;
    }
    if (lane == 31) wsum[w] = v;
    __syncthreads();
    if (tid == 0) {
        int a = 0;
#pragma unroll
        for (int q = 0; q < 8; ++q) { int t = wsum[q]; wsum[q] = a; a += t; }
    }
    __syncthreads();
    const int excl = v - ssum + wsum[w];
    if (excl < KK && KK <= excl + ssum) {
        int cum = excl;
#pragma unroll
        for (int q = 0; q < 8; ++q) {
            if (cum < KK && KK <= cum + h[q]) { tsel_s = base + q; nless_s = cum; }
            cum += h[q];
        }
    }
    __syncthreads();
    const int Tbin = tsel_s, nless = nless_s;

    // pass 2: emit bin<T directly; collect bin==T
    for (int s = tid; s < c; s += 256) {
        const unsigned long long cv = cand[s];
        const int bin = (int)(unsigned)(cv >> 53);
        if (bin < Tbin) {
            int o = atomicAdd(&outc, 1);
            g_nbr[(size_t)i*KK + o] = (int)(unsigned)cv;
        } else if (bin == Tbin) {
            int t = atomicAdd(&tcnt, 1);
            if (t < 256) tbuf[t] = cv;
        }
    }
    __syncthreads();
    const int tc = tcnt;

    if (tc <= 256) {
        int p2 = 1; while (p2 < tc) p2 <<= 1;
        for (int t = tid; t < p2; t += 256)
            if (t >= tc) tbuf[t] = ~0ull;
        for (int k = 2; k <= p2; k <<= 1) {
            for (int s = k >> 1; s > 0; s >>= 1) {
                __syncthreads();
                for (int t = tid; t < p2; t += 256) {
                    int pr = t ^ s;
                    if (pr > t) {
                        unsigned long long a = tbuf[t], bv = tbuf[pr];
                        bool up = ((t & k) == 0);
                        if ((a > bv) == up) { tbuf[t] = bv; tbuf[pr] = a; }
                    }
                }
            }
        }
        __syncthreads();
        const int need = KK - nless;
        if (tid < need)
            g_nbr[(size_t)i*KK + nless + tid] = (int)(unsigned)tbuf[tid];
    } else {
        // fallback: full bitonic sort of all candidates (overwrites everything)
        int p2 = KK; while (p2 < c) p2 <<= 1;
        for (int t = tid; t < p2; t += 256)
            if (t >= c) cand[t] = ~0ull;
        for (int k = 2; k <= p2; k <<= 1) {
            for (int s = k >> 1; s > 0; s >>= 1) {
                __syncthreads();
                for (int t = tid; t < p2; t += 256) {
                    int pr = t ^ s;
                    if (pr > t) {
                        unsigned long long a = cand[t], bv = cand[pr];
                        bool up = ((t & k) == 0);
                        if ((a > bv) == up) { cand[t] = bv; cand[pr] = a; }
                    }
                }
            }
        }
        __syncthreads();
        if (tid < KK) g_nbr[(size_t)i*KK + tid] = (int)(unsigned)cand[tid];
    }
    if (tid == 0) g_cnt[i] = KK;
}

// =====================================================================================
// Kernel 4: layer 2 + max aggregation
// =====================================================================================
__device__ __forceinline__ float dot64(const float* __restrict__ h1,
                                       const unsigned long long* __restrict__ w2p) {
    const float2* hb = (const float2*)h1;
    unsigned long long a0 = 0ull, a1 = 0ull;
#pragma unroll
    for (int h2 = 0; h2 < HH/2; h2 += 2) {
        float2 p0 = hb[h2], p1 = hb[h2 + 1];
        a0 = fma2(pack2(p0.x, p0.y), w2p[h2],     a0);
        a1 = fma2(pack2(p1.x, p1.y), w2p[h2 + 1], a1);
    }
    float l0, u0, l1, u1;
    unpack2(a0, l0, u0); unpack2(a1, l1, u1);
    return (l0 + u0) + (l1 + u1);
}

__global__ __launch_bounds__(128) void mlp_kernel(const float* __restrict__ W1,
                                                  const float* __restrict__ W2,
                                                  const float* __restrict__ b2,
                                                  float* __restrict__ out) {
    const int i = blockIdx.x;
    const int b = i / MM;
    const int tid = threadIdx.x;
    __shared__ float v[HH];
    __shared__ float h1buf[2][HH];

    unsigned long long w2p[HH/2];
#pragma unroll
    for (int h = 0; h < HH/2; ++h)
        w2p[h] = pack2(W2[(size_t)(2*h)*CO + tid], W2[(size_t)(2*h + 1)*CO + tid]);

    if (tid < HH) {
        float icx = __fdiv_rn(g_pc[(size_t)i*3 + 0], 0.2f);
        float icy = __fdiv_rn(g_pc[(size_t)i*3 + 1], 0.2f);
        float icz = __fdiv_rn(g_pc[(size_t)i*3 + 2], 0.2f);
        v[tid] = icx*W1[32*HH + tid] + icy*W1[33*HH + tid] + icz*W1[34*HH + tid];
    }
    const int cnt = g_cnt[i];
    float mx = -FLT_MAX;
    __syncthreads();

    const int which = tid >> 6, h = tid & 63;
    for (int jj = 0; jj < cnt; jj += 2) {
        int idx = jj + which;
        if (idx < cnt) {
            int nb = g_nbr[(size_t)i*KK + idx];
            h1buf[which][h] = fmaxf(g_u[((size_t)b*NP + nb)*HH + h] - v[h], 0.0f);
        }
        __syncthreads();
        mx = fmaxf(mx, dot64(h1buf[0], w2p));
        if (jj + 1 < cnt) mx = fmaxf(mx, dot64(h1buf[1], w2p));
        __syncthreads();
    }
    float res = (cnt > 0) ? (mx + b2[tid]) : 0.0f;
    out[(size_t)i*CO + tid] = res;
}

// =====================================================================================
// Kernel 5: tail outputs (centroid positions + batch vector)
// =====================================================================================
__global__ void tail_kernel(float* __restrict__ out, int has_pc, int has_batch) {
    const int i = blockIdx.x * 256 + threadIdx.x;
    if (has_pc && i < MTOT*3) out[(size_t)MTOT*CO + i] = g_pc[i];
    if (has_batch && i < MTOT) out[(size_t)MTOT*CO + (size_t)MTOT*3 + i] = (float)(i / MM);
}

extern "C" void kernel_launch(void* const* d_in, const int* in_sizes, int n_in,
                              void* d_out, int out_size) {
    const float* x   = (const float*)d_in[0];
    const float* pos = (const float*)d_in[1];
    const float* W1  = (const float*)d_in[3];
    const float* b1  = (const float*)d_in[4];
    const float* W2  = (const float*)d_in[5];
    const float* b2  = (const float*)d_in[6];
    float* out = (float*)d_out;

    cudaFuncSetAttribute(fps_kernel, cudaFuncAttributeMaxDynamicSharedMemorySize, 3*NP*4);

    fps_kernel<<<BB*GFPS, TFPS, 3*NP*4>>>(pos);
    feat_kernel<<<NTOT/4, 256>>>(x, pos, W1, b1);
    ballq_kernel<<<MTOT, 256>>>(pos);
    mlp_kernel<<<MTOT, 128>>>(W1, W2, b2, out);

    int has_pc    = out_size >= MTOT*CO + MTOT*3;
    int has_batch = out_size >= MTOT*CO + MTOT*3 + MTOT;
    if (has_pc)
        tail_kernel<<<(MTOT*3 + 255)/256, 256>>>(out, has_pc, has_batch);
}

// round 7
// speedup vs baseline: 4.4599x; 1.2259x over previous
#include <cuda_runtime.h>
#include <math.h>
#include <float.h>

#define BB   2
#define NP   16384
#define FF   32
#define MM   4096
#define KK   64
#define HH   64
#define CO   128
#define NTOT (BB*NP)
#define MTOT (BB*MM)
#define CANDMAX 2048
#define NBIN 2048

#define GFPS  8                 // CTAs per cloud (one cluster)
#define CWARPS 8                // compute warps per CTA
#define TFPS  (CWARPS*32)       // 256 threads, no comms warp
#define SHARD (NP/GFPS)         // 2048 points per CTA
#define PPT   (SHARD/TFPS)      // 8 points per thread
#define NSLOT (GFPS*CWARPS)     // 64 exchange slots

static __device__ float g_pc[MTOT*3];
static __device__ float g_u[NTOT*HH];

// ---------- packed f32x2 helpers (lane-wise identical rounding to scalar fp32) ----------
__device__ __forceinline__ unsigned long long pack2(float lo, float hi) {
    unsigned long long r;
    asm("mov.b64 %0, {%1, %2};" : "=l"(r) : "r"(__float_as_uint(lo)), "r"(__float_as_uint(hi)));
    return r;
}
__device__ __forceinline__ void unpack2(unsigned long long v, float &lo, float &hi) {
    unsigned a, b;
    asm("mov.b64 {%0, %1}, %2;" : "=r"(a), "=r"(b) : "l"(v));
    lo = __uint_as_float(a); hi = __uint_as_float(b);
}
__device__ __forceinline__ unsigned long long add2(unsigned long long a, unsigned long long b) {
    unsigned long long r; asm("add.rn.f32x2 %0, %1, %2;" : "=l"(r) : "l"(a), "l"(b)); return r;
}
__device__ __forceinline__ unsigned long long mul2(unsigned long long a, unsigned long long b) {
    unsigned long long r; asm("mul.rn.f32x2 %0, %1, %2;" : "=l"(r) : "l"(a), "l"(b)); return r;
}
__device__ __forceinline__ unsigned long long fma2(unsigned long long a, unsigned long long b, unsigned long long c) {
    unsigned long long r; asm("fma.rn.f32x2 %0, %1, %2, %3;" : "=l"(r) : "l"(a), "l"(b), "l"(c)); return r;
}

// ---------- cluster / smem sync helpers ----------
__device__ __forceinline__ unsigned cta_rank() {
    unsigned r; asm("mov.u32 %0, %%cluster_ctarank;" : "=r"(r)); return r;
}
__device__ __forceinline__ void cluster_sync_all() {
    asm volatile("barrier.cluster.arrive.aligned;" ::: "memory");
    asm volatile("barrier.cluster.wait.aligned;" ::: "memory");
}
__device__ __forceinline__ unsigned mapa_addr(unsigned local_smem_addr, unsigned target_rank) {
    unsigned raddr;
    asm volatile("mapa.shared::cluster.u32 %0, %1, %2;" : "=r"(raddr)
                 : "r"(local_smem_addr), "r"(target_rank));
    return raddr;
}
__device__ __forceinline__ void st_cluster_relaxed_u64(unsigned remote_addr, unsigned long long v) {
    asm volatile("st.relaxed.cluster.shared::cluster.b64 [%0], %1;"
                 :: "r"(remote_addr), "l"(v) : "memory");
}
__device__ __forceinline__ void ld_smem_volatile_v2(unsigned addr,
                                                    unsigned long long &a, unsigned long long &b) {
    asm volatile("ld.volatile.shared.v2.u64 {%0, %1}, [%2];"
                 : "=l"(a), "=l"(b) : "r"(addr) : "memory");
}

// =====================================================================================
// Kernel 1: exact FPS, 8-CTA cluster per cloud, 8 compute warps per CTA (no comms warp).
// Per iteration:
//   - fused packed min-update + local argmax (bit-exact non-FMA fp32 sequence)
//   - warp reduce: redux.max on d-bits (u32 order valid, d>=0), redux.min on idx among
//     tied lanes (== jnp.argmax smallest-index tie-break)
//   - lanes 0..7 push the tagged warp key [m:18|d:32|idx:14] to one cluster CTA each
//     (parallel fan-out, one issue slot)
//   - EVERY warp polls the 64 local slots (lane = 2 slots via v2.u64) until all tagged
//     m, then lane-best + split-redux -> global winner (computed redundantly per warp)
// Lap safety: all 64 slots tagged m+1 => every warp of every CTA passed poll m, so
// buffer m&1 is free for iteration m+2 (double-buffered slots).
// =====================================================================================
__global__ __launch_bounds__(TFPS, 1) __cluster_dims__(GFPS, 1, 1)
void fps_kernel(const float* __restrict__ pos) {
    extern __shared__ float sh[];
    float* sx = sh;
    float* sy = sh + NP;
    float* sz = sh + 2*NP;
    __shared__ __align__(16) unsigned long long slot[2][NSLOT];

    const int tid = threadIdx.x, lane = tid & 31, wid = tid >> 5;
    const unsigned rank = cta_rank();
    const int b = blockIdx.x / GFPS;
    const float* p = pos + (size_t)b * NP * 3;

    const unsigned slot_base = (unsigned)__cvta_generic_to_shared(&slot[0][0]);

    // init slots to impossible tags
    if (tid < 2*NSLOT) slot[tid >> 6][tid & 63] = ~0ull;

    // stage full cloud coords (SoA) into smem
    for (int i = tid; i < NP; i += TFPS) {
        sx[i] = p[3*i]; sy[i] = p[3*i+1]; sz[i] = p[3*i+2];
    }
    __syncthreads();
    cluster_sync_all();   // slots initialized + coords staged everywhere

    // per-lane remote address: lane g pushes this warp's key into CTA g's slot column
    unsigned raddr_g = 0;
    if (lane < GFPS)
        raddr_g = mapa_addr(slot_base + (rank*CWARPS + (unsigned)wid)*8u, (unsigned)lane);

    const int jbase = (int)rank * SHARD + tid;
    float mx[PPT], my[PPT], mz[PPT], d[PPT];
    const float x0 = sx[0], y0 = sy[0], z0 = sz[0];
    float bd = -FLT_MAX; int bj = 0;
#pragma unroll
    for (int k = 0; k < PPT; ++k) {
        int j = jbase + k*TFPS;
        mx[k] = sx[j]; my[k] = sy[j]; mz[k] = sz[j];
        float dx = __fsub_rn(mx[k], x0);
        float dy = __fsub_rn(my[k], y0);
        float dz = __fsub_rn(mz[k], z0);
        d[k] = __fadd_rn(__fadd_rn(__fmul_rn(dx,dx), __fmul_rn(dy,dy)), __fmul_rn(dz,dz));
        if (d[k] > bd) { bd = d[k]; bj = j; }
    }
    if (rank == 0 && tid == 0) {
        g_pc[((size_t)b*MM + 0)*3 + 0] = x0;
        g_pc[((size_t)b*MM + 0)*3 + 1] = y0;
        g_pc[((size_t)b*MM + 0)*3 + 2] = z0;
    }

    for (int m = 1; m < MM; ++m) {
        const int buf = m & 1;
        const unsigned mt = (unsigned)m;
        const unsigned boff = (unsigned)buf * (NSLOT*8u);
        // --- warp reduce: max d-bits, min idx among ties ---
        const unsigned mb   = __float_as_uint(bd);
        const unsigned wmax = __reduce_max_sync(0xffffffffu, mb);
        const unsigned ci   = (mb == wmax) ? (unsigned)bj : 0xFFFFFFFFu;
        const unsigned widx = __reduce_min_sync(0xffffffffu, ci);
        // --- parallel fan-out: lanes 0..7 each push to one CTA ---
        const unsigned long long key =
            ((unsigned long long)mt << 46) |
            ((unsigned long long)wmax << 14) | widx;
        if (lane < GFPS) st_cluster_relaxed_u64(raddr_g + boff, key);
        // --- poll 64 local slots (2 per lane) until all tagged m ---
        const unsigned sa = slot_base + boff + (unsigned)lane * 16u;
        unsigned long long k0, k1;
        for (;;) {
            ld_smem_volatile_v2(sa, k0, k1);
            bool ok = ((unsigned)(k0 >> 46) == mt) & ((unsigned)(k1 >> 46) == mt);
            if (__all_sync(0xffffffffu, ok)) break;
        }
        // --- lane-local best of 2 slots: larger d, then smaller idx ---
        const unsigned d0 = (unsigned)(k0 >> 14), d1 = (unsigned)(k1 >> 14);
        const unsigned i0 = (unsigned)(k0 & 0x3FFFull), i1 = (unsigned)(k1 & 0x3FFFull);
        unsigned dl, il;
        if (d0 > d1)      { dl = d0; il = i0; }
        else if (d1 > d0) { dl = d1; il = i1; }
        else              { dl = d0; il = min(i0, i1); }
        const unsigned wd = __reduce_max_sync(0xffffffffu, dl);
        const unsigned c2 = (dl == wd) ? il : 0xFFFFFFFFu;
        const unsigned wi = __reduce_min_sync(0xffffffffu, c2);
        const float wx = sx[wi], wy = sy[wi], wz = sz[wi];
        if (rank == 0 && tid == 0) {
            g_pc[((size_t)b*MM + m)*3 + 0] = wx;
            g_pc[((size_t)b*MM + m)*3 + 1] = wy;
            g_pc[((size_t)b*MM + m)*3 + 2] = wz;
        }
        // --- fused packed min-update + next argmax (exact op sequence) ---
        const unsigned long long nwx = pack2(-wx, -wx);
        const unsigned long long nwy = pack2(-wy, -wy);
        const unsigned long long nwz = pack2(-wz, -wz);
        bd = -FLT_MAX; bj = 0;
#pragma unroll
        for (int kk = 0; kk < PPT/2; ++kk) {
            unsigned long long dx = add2(pack2(mx[2*kk], mx[2*kk+1]), nwx);
            unsigned long long dy = add2(pack2(my[2*kk], my[2*kk+1]), nwy);
            unsigned long long dz = add2(pack2(mz[2*kk], mz[2*kk+1]), nwz);
            unsigned long long s  = add2(add2(mul2(dx,dx), mul2(dy,dy)), mul2(dz,dz));
            float s0, s1; unpack2(s, s0, s1);
            d[2*kk]   = fminf(d[2*kk],   s0);
            d[2*kk+1] = fminf(d[2*kk+1], s1);
            if (d[2*kk]   > bd) { bd = d[2*kk];   bj = jbase + (2*kk)*TFPS; }
            if (d[2*kk+1] > bd) { bd = d[2*kk+1]; bj = jbase + (2*kk+1)*TFPS; }
        }
    }
    cluster_sync_all();   // keep CTAs resident until all exchanges consumed
}

// =====================================================================================
// Kernel 2: per-point layer-1 partials  u_j = x_j@W1[:32] + p_j@W1[32:35] + b1
// =====================================================================================
__global__ __launch_bounds__(256) void feat_kernel(const float* __restrict__ x,
                                                   const float* __restrict__ pos,
                                                   const float* __restrict__ W1,
                                                   const float* __restrict__ b1) {
    __shared__ float xs[4][FF];
    __shared__ float ps[4][3];
    const int j0 = blockIdx.x * 4;
    const int tid = threadIdx.x;
    if (tid < 128) xs[tid >> 5][tid & 31] = x[(size_t)(j0 + (tid >> 5))*FF + (tid & 31)];
    if (tid < 12)  ps[tid / 3][tid % 3]   = pos[(size_t)j0*3 + tid];
    __syncthreads();
    const int pt = tid >> 6, h = tid & 63;
    float acc = b1[h];
#pragma unroll
    for (int f = 0; f < FF; ++f) acc += xs[pt][f] * W1[f*HH + h];
    acc += ps[pt][0] * W1[32*HH + h];
    acc += ps[pt][1] * W1[33*HH + h];
    acc += ps[pt][2] * W1[34*HH + h];
    g_u[(size_t)(j0 + pt)*HH + h] = acc;
}

// =====================================================================================
// Kernel 3 (FUSED): ball query (radix-select top-K) + layer-2 MLP + max aggregation.
// Neighbors stay in smem; 256 threads: channel = tid&127, half = tid>>7; each half
// processes alternating neighbor pairs; final smem max-combine (order-invariant).
// =====================================================================================
__device__ __forceinline__ float dot64(const float* __restrict__ h1,
                                       const unsigned long long* __restrict__ w2p) {
    const float2* hb = (const float2*)h1;
    unsigned long long a0 = 0ull, a1 = 0ull;
#pragma unroll
    for (int h2 = 0; h2 < HH/2; h2 += 2) {
        float2 p0 = hb[h2], p1 = hb[h2 + 1];
        a0 = fma2(pack2(p0.x, p0.y), w2p[h2],     a0);
        a1 = fma2(pack2(p1.x, p1.y), w2p[h2 + 1], a1);
    }
    float l0, u0, l1, u1;
    unpack2(a0, l0, u0); unpack2(a1, l1, u1);
    return (l0 + u0) + (l1 + u1);
}

__global__ __launch_bounds__(256) void ballq_mlp_kernel(const float* __restrict__ pos,
                                                        const float* __restrict__ W1,
                                                        const float* __restrict__ W2,
                                                        const float* __restrict__ b2,
                                                        float* __restrict__ out) {
    const float R2 = (float)(0.2 * 0.2);
    const int i = blockIdx.x;
    const int b = i / MM;
    __shared__ unsigned long long cand[CANDMAX];
    __shared__ int hist[NBIN];
    __shared__ unsigned long long tbuf[256];
    __shared__ int nbr[KK];
    __shared__ float vsh[HH];
    __shared__ float h1buf[4][HH];
    __shared__ float mxsh[128];
    __shared__ int cnt, outc, tcnt, tsel_s, nless_s, fincnt;
    __shared__ int wsum[8];
    const int tid = threadIdx.x;
    const int lane = tid & 31, w = tid >> 5;
    if (tid == 0) { cnt = 0; outc = 0; tcnt = 0; }
    const float cx = g_pc[(size_t)i*3 + 0];
    const float cy = g_pc[(size_t)i*3 + 1];
    const float cz = g_pc[(size_t)i*3 + 2];
    for (int t = tid; t < NBIN; t += 256) hist[t] = 0;
    if (tid < HH) {
        float icx = __fdiv_rn(cx, 0.2f);
        float icy = __fdiv_rn(cy, 0.2f);
        float icz = __fdiv_rn(cz, 0.2f);
        vsh[tid] = icx*W1[32*HH + tid] + icy*W1[33*HH + tid] + icz*W1[34*HH + tid];
    }
    __syncthreads();
    const float* p = pos + (size_t)b * NP * 3;
    for (int j = tid; j < NP; j += 256) {
        float dx = __fsub_rn(cx, p[3*j]);
        float dy = __fsub_rn(cy, p[3*j+1]);
        float dz = __fsub_rn(cz, p[3*j+2]);
        float d2 = __fadd_rn(__fadd_rn(__fmul_rn(dx,dx), __fmul_rn(dy,dy)), __fmul_rn(dz,dz));
        if (d2 <= R2) {
            int sl = atomicAdd(&cnt, 1);
            if (sl < CANDMAX)
                cand[sl] = ((unsigned long long)__float_as_uint(d2) << 32) | (unsigned)j;
        }
    }
    __syncthreads();
    const int c = min(cnt, CANDMAX);

    if (c <= KK) {
        for (int s = tid; s < c; s += 256) nbr[s] = (int)(unsigned)cand[s];
        if (tid == 0) fincnt = c;
    } else {
        // histogram on top-11 bits of d2 (bits 63..53 of the key)
        for (int s = tid; s < c; s += 256)
            atomicAdd(&hist[(unsigned)(cand[s] >> 53)], 1);
        __syncthreads();
        // CTA scan over 2048 bins (8 per thread) to locate threshold bin
        const int base = tid * 8;
        int h[8]; int ssum = 0;
#pragma unroll
        for (int q = 0; q < 8; ++q) { h[q] = hist[base + q]; ssum += h[q]; }
        int v = ssum;
#pragma unroll
        for (int o = 1; o < 32; o <<= 1) {
            int n2 = __shfl_up_sync(0xffffffffu, v, o);
            if (lane >= o) v += n2;
        }
        if (lane == 31) wsum[w] = v;
        __syncthreads();
        if (tid == 0) {
            int a = 0;
#pragma unroll
            for (int q = 0; q < 8; ++q) { int t = wsum[q]; wsum[q] = a; a += t; }
        }
        __syncthreads();
        const int excl = v - ssum + wsum[w];
        if (excl < KK && KK <= excl + ssum) {
            int cum = excl;
#pragma unroll
            for (int q = 0; q < 8; ++q) {
                if (cum < KK && KK <= cum + h[q]) { tsel_s = base + q; nless_s = cum; }
                cum += h[q];
            }
        }
        __syncthreads();
        const int Tbin = tsel_s, nless = nless_s;
        // pass 2: emit bin<T directly; collect bin==T
        for (int s = tid; s < c; s += 256) {
            const unsigned long long cv = cand[s];
            const int bin = (int)(unsigned)(cv >> 53);
            if (bin < Tbin) {
                int o = atomicAdd(&outc, 1);
                nbr[o] = (int)(unsigned)cv;
            } else if (bin == Tbin) {
                int t = atomicAdd(&tcnt, 1);
                if (t < 256) tbuf[t] = cv;
            }
        }
        __syncthreads();
        const int tc = tcnt;
        if (tc <= 256) {
            int p2 = 1; while (p2 < tc) p2 <<= 1;
            for (int t = tid; t < p2; t += 256)
                if (t >= tc) tbuf[t] = ~0ull;
            for (int k = 2; k <= p2; k <<= 1) {
                for (int s = k >> 1; s > 0; s >>= 1) {
                    __syncthreads();
                    for (int t = tid; t < p2; t += 256) {
                        int pr = t ^ s;
                        if (pr > t) {
                            unsigned long long a = tbuf[t], bv = tbuf[pr];
                            bool up = ((t & k) == 0);
                            if ((a > bv) == up) { tbuf[t] = bv; tbuf[pr] = a; }
                        }
                    }
                }
            }
            __syncthreads();
            const int need = KK - nless;
            if (tid < need) nbr[nless + tid] = (int)(unsigned)tbuf[tid];
        } else {
            // fallback: full bitonic sort of all candidates
            int p2 = KK; while (p2 < c) p2 <<= 1;
            for (int t = tid; t < p2; t += 256)
                if (t >= c) cand[t] = ~0ull;
            for (int k = 2; k <= p2; k <<= 1) {
                for (int s = k >> 1; s > 0; s >>= 1) {
                    __syncthreads();
                    for (int t = tid; t < p2; t += 256) {
                        int pr = t ^ s;
                        if (pr > t) {
                            unsigned long long a = cand[t], bv = cand[pr];
                            bool up = ((t & k) == 0);
                            if ((a > bv) == up) { cand[t] = bv; cand[pr] = a; }
                        }
                    }
                }
            }
            __syncthreads();
            if (tid < KK) nbr[tid] = (int)(unsigned)cand[tid];
        }
        if (tid == 0) fincnt = KK;
    }
    __syncthreads();
    const int n = fincnt;

    // ---------------- MLP phase: 256 threads, channel = tid&127, half = tid>>7 -------
    const int ch = tid & 127, half = tid >> 7;
    unsigned long long w2p[HH/2];
#pragma unroll
    for (int h = 0; h < HH/2; ++h)
        w2p[h] = pack2(W2[(size_t)(2*h)*CO + ch], W2[(size_t)(2*h + 1)*CO + ch]);

    float mxv = -FLT_MAX;
    for (int jj = 0; jj < n; jj += 4) {
        const int idx = jj + (tid >> 6);
        if (idx < n) {
            const int nb = nbr[idx];
            h1buf[tid >> 6][tid & 63] =
                fmaxf(g_u[((size_t)b*NP + nb)*HH + (tid & 63)] - vsh[tid & 63], 0.0f);
        }
        __syncthreads();
        const int r = half * 2;
        if (jj + r < n)     mxv = fmaxf(mxv, dot64(h1buf[r],     w2p));
        if (jj + r + 1 < n) mxv = fmaxf(mxv, dot64(h1buf[r + 1], w2p));
        __syncthreads();
    }
    if (half == 1) mxsh[ch] = mxv;
    __syncthreads();
    if (half == 0) {
        float o = (n > 1) ? fmaxf(mxv, mxsh[ch]) : mxv;
        out[(size_t)i*CO + ch] = (n > 0) ? (o + b2[ch]) : 0.0f;
    }
}

// =====================================================================================
// Kernel 4: tail outputs (centroid positions + batch vector)
// =====================================================================================
__global__ void tail_kernel(float* __restrict__ out, int has_pc, int has_batch) {
    const int i = blockIdx.x * 256 + threadIdx.x;
    if (has_pc && i < MTOT*3) out[(size_t)MTOT*CO + i] = g_pc[i];
    if (has_batch && i < MTOT) out[(size_t)MTOT*CO + (size_t)MTOT*3 + i] = (float)(i / MM);
}

extern "C" void kernel_launch(void* const* d_in, const int* in_sizes, int n_in,
                              void* d_out, int out_size) {
    const float* x   = (const float*)d_in[0];
    const float* pos = (const float*)d_in[1];
    const float* W1  = (const float*)d_in[3];
    const float* b1  = (const float*)d_in[4];
    const float* W2  = (const float*)d_in[5];
    const float* b2  = (const float*)d_in[6];
    float* out = (float*)d_out;

    cudaFuncSetAttribute(fps_kernel, cudaFuncAttributeMaxDynamicSharedMemorySize, 3*NP*4);

    fps_kernel<<<BB*GFPS, TFPS, 3*NP*4>>>(pos);
    feat_kernel<<<NTOT/4, 256>>>(x, pos, W1, b1);
    ballq_mlp_kernel<<<MTOT, 256>>>(pos, W1, W2, b2, out);

    int has_pc    = out_size >= MTOT*CO + MTOT*3;
    int has_batch = out_size >= MTOT*CO + MTOT*3 + MTOT;
    if (has_pc)
        tail_kernel<<<(MTOT*3 + 255)/256, 256>>>(out, has_pc, has_batch);
}